// round 8
// baseline (speedup 1.0000x reference)
#include <cuda_runtime.h>
#include <cuda_bf16.h>
#include <math.h>

#define D 128
#define S 64
#define G 256
#define NMAX 400000

#define LDH 136    // bf16 stride, activation tiles: conflict-free
#define LDWB 72    // bf16 stride, [n][k] weight tiles + sub tile: conflict-free
#define NT 256

typedef __nv_bfloat16 bf16;

// ---------------- persistent device scratch (allocation-free) ----------------
__device__ bf16 g_hb[(size_t)NMAX * D];
__device__ bf16 g_subb[(size_t)NMAX * S];
__device__ bf16 g_W1b[D * S];          // [n=128][k=64] transposed
__device__ bf16 g_Wgb[4 * D * S];      // [ck][n][k]
__device__ bf16 g_Ws1b[4 * D * S];     // [ck][n][k]
__device__ bf16 g_hfb[(size_t)NMAX * D];   // h_fused bf16
__device__ bf16 g_Z1b[(size_t)NMAX * D];   // Z1 bf16
__device__ float g_hs[G * D];
__device__ float g_hss[G * D];
__device__ float g_cnt[G];
__device__ float g_bn1sum[D], g_bn1sq[D];
__device__ float g_bn2sum[D], g_bn2sq[D];
__device__ float g_a1[D], g_c1[D], g_a2[D], g_c2[D];
__device__ float g_gm[G * D], g_gisd[G * D];
__device__ float g_num[G * D];
__device__ float g_den[G];

extern __shared__ float dynsmem[];

// ---------------- helpers ----------------
__device__ __forceinline__ void cp16(void* dst_smem, const void* src) {
    unsigned a = (unsigned)__cvta_generic_to_shared(dst_smem);
    asm volatile("cp.async.cg.shared.global [%0], [%1], 16;\n" :: "r"(a), "l"(src));
}
__device__ __forceinline__ void cp_commit() { asm volatile("cp.async.commit_group;\n"); }
template <int NN> __device__ __forceinline__ void cp_wait() {
    asm volatile("cp.async.wait_group %0;\n" :: "n"(NN));
}

__device__ __forceinline__ unsigned pk(float lo, float hi) {
    unsigned r;
    asm("cvt.rn.bf16x2.f32 %0, %1, %2;" : "=r"(r) : "f"(hi), "f"(lo));
    return r;
}
__device__ __forceinline__ void upk(unsigned v, float& lo, float& hi) {
    lo = __uint_as_float(v << 16);
    hi = __uint_as_float(v & 0xffff0000u);
}

__device__ __forceinline__ void mma_bf16(float* d, const unsigned* a, unsigned b0, unsigned b1) {
    asm volatile(
        "mma.sync.aligned.m16n8k16.row.col.f32.bf16.bf16.f32 "
        "{%0,%1,%2,%3}, {%4,%5,%6,%7}, {%8,%9}, {%0,%1,%2,%3};\n"
        : "+f"(d[0]), "+f"(d[1]), "+f"(d[2]), "+f"(d[3])
        : "r"(a[0]), "r"(a[1]), "r"(a[2]), "r"(a[3]), "r"(b0), "r"(b1));
}

// 64-deep K chunk; warp computes 32(M)x64(N) of a 128x128 tile. 8 warps.
__device__ __forceinline__ void mma_chunk(float (&acc)[2][8][4],
                                          const bf16* sA, int lda, int kcol0,
                                          const bf16* sB, int wm, int wn, int lane) {
    int g4 = lane >> 2, t4 = lane & 3;
#pragma unroll
    for (int ks = 0; ks < 4; ks++) {
        int kk = ks * 16;
        unsigned a[2][4];
#pragma unroll
        for (int mt = 0; mt < 2; mt++) {
            const bf16* p = sA + (wm * 32 + mt * 16 + g4) * lda + kcol0 + kk + 2 * t4;
            a[mt][0] = *(const unsigned*)p;
            a[mt][1] = *(const unsigned*)(p + 8 * lda);
            a[mt][2] = *(const unsigned*)(p + 8);
            a[mt][3] = *(const unsigned*)(p + 8 * lda + 8);
        }
#pragma unroll
        for (int nt = 0; nt < 8; nt++) {
            const bf16* q = sB + (wn * 64 + nt * 8 + g4) * LDWB + kk + 2 * t4;
            unsigned b0 = *(const unsigned*)q;
            unsigned b1 = *(const unsigned*)(q + 8);
            mma_bf16(acc[0][nt], a[0], b0, b1);
            mma_bf16(acc[1][nt], a[1], b0, b1);
        }
    }
}

__device__ __forceinline__ void load_wchunk(bf16* buf, const bf16* Wsrc, int tid) {
#pragma unroll
    for (int j = 0; j < 4; j++) {
        int idx = tid + j * NT;
        int n = idx >> 3, f = idx & 7;
        cp16(buf + n * LDWB + f * 8, Wsrc + n * 64 + f * 8);
    }
}

// ---------------- K0: zero accumulators ----------------
__global__ void k_zero() {
    int i = blockIdx.x * blockDim.x + threadIdx.x;
    if (i < G * D) { g_hs[i] = 0.f; g_hss[i] = 0.f; g_num[i] = 0.f; }
    if (i < G) { g_cnt[i] = 0.f; g_den[i] = 0.f; }
    if (i < D) { g_bn1sum[i] = 0.f; g_bn1sq[i] = 0.f; g_bn2sum[i] = 0.f; g_bn2sq[i] = 0.f; }
}

// ---------------- K-prep: weights -> bf16, transposed [n][k] chunks ----------------
__global__ void k_prep(const float* __restrict__ W1, const float* __restrict__ Wg,
                       const float* __restrict__ Ws1) {
    int i = blockIdx.x * blockDim.x + threadIdx.x;
    if (i < D * S) {
        int n = i / S, k = i % S;
        g_W1b[i] = __float2bfloat16(W1[k * D + n]);
    }
    if (i < 4 * D * S) {
        int ck = i / (D * S), rem = i % (D * S);
        int n = rem / S, kl = rem % S;
        g_Wgb[i] = __float2bfloat16(Wg[(ck * S + kl) * D + n]);
        g_Ws1b[i] = __float2bfloat16(Ws1[(ck * S + kl) * D + n]);
    }
}

// ---------------- K1: single-pass h (stats + bf16 emit) + sub emit + BN1 stats ----------------
__global__ __launch_bounds__(NT, 2) void k_pass1(const float* __restrict__ h,
                                                 const float* __restrict__ sub,
                                                 const int* __restrict__ batch,
                                                 const float* __restrict__ b1, int N) {
    bf16* Sb = (bf16*)dynsmem;                 // [128][LDWB]
    bf16* Wp = Sb + 128 * LDWB;                // [128][LDWB]
    int* gid = (int*)(Wp + 128 * LDWB);        // [128]
    int tid = threadIdx.x, lane = tid & 31, warp = tid >> 5;
    int wm = warp >> 1, wn = warp & 1;
    int r0 = blockIdx.x * 128;

    load_wchunk(Wp, g_W1b, tid);
    cp_commit();
    if (tid < 128) gid[tid] = batch[min(r0 + tid, N - 1)];

    // sub: fp32 -> bf16 into Sb smem + g_subb global
    for (int i = tid; i < 128 * 32; i += NT) {
        int r = i >> 5, p2 = i & 31;
        int rr = min(r0 + r, N - 1);
        float2 v = *(const float2*)(sub + (size_t)rr * S + p2 * 2);
        unsigned w = pk(v.x, v.y);
        *(unsigned*)(Sb + r * LDWB + p2 * 2) = w;
        if (r0 + r < N) *(unsigned*)(g_subb + (size_t)(r0 + r) * S + p2 * 2) = w;
    }
    __syncthreads();   // gid visible before the stats loop

    // --- h: ONE fp32 read -> (bf16 emit) + (segment stats, per-thread run-length) ---
    // thread owns column pair c = 2*(tid&63), rows (tid>>6) + 4*j, j=0..31 (in order)
    {
        int p2 = tid & 63;
        int c = p2 * 2;
        int rstart = tid >> 6;                 // 0..3
        float s0 = 0.f, s1 = 0.f, q0 = 0.f, q1 = 0.f, cf = 0.f;
        int cur = gid[rstart];
#pragma unroll 4
        for (int j = 0; j < 32; j++) {
            int r = rstart + 4 * j;
            int rg = r0 + r;
            if (rg < N) {
                float2 v = *(const float2*)(h + (size_t)rg * D + c);
                *(unsigned*)(g_hb + (size_t)rg * D + c) = pk(v.x, v.y);
                int g = gid[r];
                if (g != cur) {
                    atomicAdd(&g_hs[cur * D + c], s0);
                    atomicAdd(&g_hs[cur * D + c + 1], s1);
                    atomicAdd(&g_hss[cur * D + c], q0);
                    atomicAdd(&g_hss[cur * D + c + 1], q1);
                    if (p2 == 0) atomicAdd(&g_cnt[cur], cf);
                    s0 = s1 = q0 = q1 = cf = 0.f;
                    cur = g;
                }
                s0 += v.x; s1 += v.y;
                q0 += v.x * v.x; q1 += v.y * v.y;
                cf += 1.f;
            }
        }
        atomicAdd(&g_hs[cur * D + c], s0);
        atomicAdd(&g_hs[cur * D + c + 1], s1);
        atomicAdd(&g_hss[cur * D + c], q0);
        atomicAdd(&g_hss[cur * D + c + 1], q1);
        if (p2 == 0) atomicAdd(&g_cnt[cur], cf);
    }

    // --- BN1 stats via bf16 mma from accumulators ---
    cp_wait<0>();
    __syncthreads();

    float acc[2][8][4];
#pragma unroll
    for (int mt = 0; mt < 2; mt++)
#pragma unroll
        for (int nt = 0; nt < 8; nt++)
#pragma unroll
            for (int e = 0; e < 4; e++) acc[mt][nt][e] = 0.f;

    mma_chunk(acc, Sb, LDWB, 0, Wp, wm, wn, lane);

    int g4 = lane >> 2, t4 = lane & 3;
#pragma unroll
    for (int nt = 0; nt < 8; nt++)
#pragma unroll
        for (int par = 0; par < 2; par++) {
            int ccol = wn * 64 + nt * 8 + t4 * 2 + par;
            float bb = b1[ccol];
            float s1 = 0.f, s2 = 0.f;
#pragma unroll
            for (int mt = 0; mt < 2; mt++)
#pragma unroll
                for (int rh = 0; rh < 2; rh++) {
                    int r = r0 + wm * 32 + mt * 16 + g4 + rh * 8;
                    float val = acc[mt][nt][rh * 2 + par] + bb;
                    if (r < N) { s1 += val; s2 += val * val; }
                }
#pragma unroll
            for (int o = 4; o < 32; o <<= 1) {
                s1 += __shfl_xor_sync(0xffffffffu, s1, o);
                s2 += __shfl_xor_sync(0xffffffffu, s2, o);
            }
            if (g4 == 0) {
                atomicAdd(&g_bn1sum[ccol], s1);
                atomicAdd(&g_bn1sq[ccol], s2);
            }
        }
}

// ---------------- K2: graph stat finalize + BN1 finalize ----------------
__global__ void k_mid(const float* __restrict__ gam, const float* __restrict__ bet, float invN) {
    int i = blockIdx.x * blockDim.x + threadIdx.x;
    if (i < G * D) {
        int g = i / D;
        float cnt = fmaxf(g_cnt[g], 1.f);
        float m = g_hs[i] / cnt;
        float v = g_hss[i] / cnt - m * m;
        float sd = sqrtf(fmaxf(v, 1e-8f));
        g_gm[i] = m;
        g_gisd[i] = 1.f / (sd + 1e-8f);
    }
    if (blockIdx.x == 0 && threadIdx.x < D) {
        int c = threadIdx.x;
        float mu = g_bn1sum[c] * invN;
        float var = g_bn1sq[c] * invN - mu * mu;
        float inv = rsqrtf(var + 1e-5f);
        g_a1[c] = gam[c] * inv;
        g_c1[c] = bet[c] - mu * gam[c] * inv;
    }
}

__global__ void k_bnfin2(const float* __restrict__ gam, const float* __restrict__ bet, float invN) {
    int i = threadIdx.x;
    float mu = g_bn2sum[i] * invN;
    float var = g_bn2sq[i] * invN - mu * mu;
    float inv = rsqrtf(var + 1e-5f);
    g_a2[i] = gam[i] * inv;
    g_c2[i] = bet[i] - mu * gam[i] * inv;
}

// ---------------- K3: big fused pass (bf16 tiles, 2 CTAs/SM) ----------------
__global__ __launch_bounds__(NT, 2) void k_fused(
    const int* __restrict__ batch,
    const float* __restrict__ b1, const float* __restrict__ bg,
    const float* __restrict__ bs1, int N) {
    bf16* Hb = (bf16*)dynsmem;                 // [128][LDH]  h -> h_dev
    bf16* Eb = Hb + 128 * LDH;                 // [128][LDH]  sub_e -> h_fused
    bf16* Wq = Eb + 128 * LDH;                 // [128][LDWB] sub, then pong
    bf16* Wp = Wq + 128 * LDWB;                // [128][LDWB] W1, then ping
    float* pa1 = (float*)(Wp + 128 * LDWB);
    float* pc1 = pa1 + D;
    float* pb1 = pc1 + D;
    float* pbg = pb1 + D;
    float* pbs1 = pbg + D;
    int* gid = (int*)(pbs1 + D);               // [128]

    int tid = threadIdx.x, lane = tid & 31, warp = tid >> 5;
    int wm = warp >> 1, wn = warp & 1;
    int g4 = lane >> 2, t4 = lane & 3;
    int r0 = blockIdx.x * 128;

#pragma unroll
    for (int j = 0; j < 4; j++) {
        int idx = tid + j * NT;
        int r = idx >> 3, f = idx & 7;
        int rr = min(r0 + r, N - 1);
        cp16(Wq + r * LDWB + f * 8, g_subb + (size_t)rr * S + f * 8);
    }
    load_wchunk(Wp, g_W1b, tid);
    cp_commit();
#pragma unroll
    for (int j = 0; j < 8; j++) {
        int idx = tid + j * NT;
        int r = idx >> 4, f = idx & 15;
        int rr = min(r0 + r, N - 1);
        cp16(Hb + r * LDH + f * 8, g_hb + (size_t)rr * D + f * 8);
    }
    cp_commit();

    if (tid < 128) {
        pa1[tid] = g_a1[tid]; pc1[tid] = g_c1[tid]; pb1[tid] = b1[tid];
        pbg[tid] = bg[tid]; pbs1[tid] = bs1[tid];
        gid[tid] = batch[min(r0 + tid, N - 1)];
    }

    float acc[2][8][4];
#pragma unroll
    for (int mt = 0; mt < 2; mt++)
#pragma unroll
        for (int nt = 0; nt < 8; nt++)
#pragma unroll
            for (int e = 0; e < 4; e++) acc[mt][nt][e] = 0.f;

    // ---- mma1: X1 = sub @ W1 ----
    cp_wait<1>();
    __syncthreads();
    mma_chunk(acc, Wq, LDWB, 0, Wp, wm, wn, lane);

    // sub_e epilogue -> Eb
#pragma unroll
    for (int mt = 0; mt < 2; mt++)
#pragma unroll
        for (int nt = 0; nt < 8; nt++)
#pragma unroll
            for (int rh = 0; rh < 2; rh++) {
                int r = wm * 32 + mt * 16 + g4 + rh * 8;
                int c = wn * 64 + nt * 8 + 2 * t4;
                float x0 = acc[mt][nt][rh * 2 + 0] + pb1[c];
                float x1 = acc[mt][nt][rh * 2 + 1] + pb1[c + 1];
                float e0 = fmaxf(pa1[c] * x0 + pc1[c], 0.f);
                float e1 = fmaxf(pa1[c + 1] * x1 + pc1[c + 1], 0.f);
                *(unsigned*)(Eb + r * LDH + c) = pk(e0, e1);
                acc[mt][nt][rh * 2 + 0] = 0.f;
                acc[mt][nt][rh * 2 + 1] = 0.f;
            }
    __syncthreads();

    const bf16* Wtab[8] = { g_Wgb, g_Wgb + 8192, g_Wgb + 16384, g_Wgb + 24576,
                            g_Ws1b, g_Ws1b + 8192, g_Ws1b + 16384, g_Ws1b + 24576 };
    load_wchunk(Wp, Wtab[0], tid); cp_commit();
    load_wchunk(Wq, Wtab[1], tid); cp_commit();

#pragma unroll 1
    for (int k = 0; k < 8; k++) {
        if (k < 6) cp_wait<1>(); else cp_wait<0>();
        __syncthreads();
        bf16* buf = (k & 1) ? Wq : Wp;
        const bf16* A = (k < 2) ? Hb : (k < 6) ? Eb : Hb;
        mma_chunk(acc, A, LDH, (k & 1) * 64, buf, wm, wn, lane);
        __syncthreads();
        if (k + 2 < 8) { load_wchunk(buf, Wtab[k + 2], tid); cp_commit(); }

        if (k == 3) {
            // gate epilogue: h_fused = h + sigmoid(acc+bg)*sub_e  (bf16 out)
#pragma unroll
            for (int mt = 0; mt < 2; mt++)
#pragma unroll
                for (int nt = 0; nt < 8; nt++)
#pragma unroll
                    for (int rh = 0; rh < 2; rh++) {
                        int r = wm * 32 + mt * 16 + g4 + rh * 8;
                        int c = wn * 64 + nt * 8 + 2 * t4;
                        float gx0 = acc[mt][nt][rh * 2 + 0] + pbg[c];
                        float gx1 = acc[mt][nt][rh * 2 + 1] + pbg[c + 1];
                        float gt0 = 1.f / (1.f + expf(-gx0));
                        float gt1 = 1.f / (1.f + expf(-gx1));
                        float h0, h1, s0, s1;
                        upk(*(const unsigned*)(Hb + r * LDH + c), h0, h1);
                        upk(*(const unsigned*)(Eb + r * LDH + c), s0, s1);
                        unsigned w = pk(h0 + gt0 * s0, h1 + gt1 * s1);
                        if (r0 + r < N)
                            *(unsigned*)(g_hfb + (size_t)(r0 + r) * D + c) = w;
                        *(unsigned*)(Eb + r * LDH + c) = w;
                        acc[mt][nt][rh * 2 + 0] = 0.f;
                        acc[mt][nt][rh * 2 + 1] = 0.f;
                    }
            __syncthreads();
            // Hb: h -> h_dev
            for (int i = tid; i < 128 * 64; i += NT) {
                int r = i >> 6, c = (i & 63) * 2;
                int g = gid[r];
                float h0, h1;
                upk(*(const unsigned*)(Hb + r * LDH + c), h0, h1);
                float2 m2 = *(const float2*)(g_gm + g * D + c);
                float2 i2 = *(const float2*)(g_gisd + g * D + c);
                *(unsigned*)(Hb + r * LDH + c) = pk((h0 - m2.x) * i2.x, (h1 - m2.y) * i2.y);
            }
            __syncthreads();
        }
    }

    // mma3 epilogue: Z1 bf16 to global + BN2 stats from fp32 accumulators
#pragma unroll
    for (int mt = 0; mt < 2; mt++)
#pragma unroll
        for (int nt = 0; nt < 8; nt++)
#pragma unroll
            for (int rh = 0; rh < 2; rh++) {
                int r = wm * 32 + mt * 16 + g4 + rh * 8;
                int c = wn * 64 + nt * 8 + 2 * t4;
                if (r0 + r < N) {
                    float z0 = acc[mt][nt][rh * 2 + 0] + pbs1[c];
                    float z1 = acc[mt][nt][rh * 2 + 1] + pbs1[c + 1];
                    *(unsigned*)(g_Z1b + (size_t)(r0 + r) * D + c) = pk(z0, z1);
                }
            }
#pragma unroll
    for (int nt = 0; nt < 8; nt++)
#pragma unroll
        for (int par = 0; par < 2; par++) {
            int ccol = wn * 64 + nt * 8 + 2 * t4 + par;
            float bb = pbs1[ccol];
            float s1 = 0.f, s2 = 0.f;
#pragma unroll
            for (int mt = 0; mt < 2; mt++)
#pragma unroll
                for (int rh = 0; rh < 2; rh++) {
                    int r = r0 + wm * 32 + mt * 16 + g4 + rh * 8;
                    float val = acc[mt][nt][rh * 2 + par] + bb;
                    if (r < N) { s1 += val; s2 += val * val; }
                }
#pragma unroll
            for (int o = 4; o < 32; o <<= 1) {
                s1 += __shfl_xor_sync(0xffffffffu, s1, o);
                s2 += __shfl_xor_sync(0xffffffffu, s2, o);
            }
            if (g4 == 0) {
                atomicAdd(&g_bn2sum[ccol], s1);
                atomicAdd(&g_bn2sq[ccol], s2);
            }
        }
}

// ---------------- K5: logits + exp + weighted segment sums (bf16 inputs) ----------------
__global__ __launch_bounds__(256) void k_score(const int* __restrict__ batch,
                                               const float* __restrict__ Ws2,
                                               const float* __restrict__ bs2, int N) {
    __shared__ float es[256];
    __shared__ int gid[256];
    int tid = threadIdx.x, lane = tid & 31, warp = tid >> 5;
    int r0 = blockIdx.x * 256;
    int nr = min(256, N - r0);
    gid[tid] = batch[min(r0 + min(tid, nr - 1), N - 1)];

    // lane owns columns 4*lane .. 4*lane+3
    float a2v[4], c2v[4], wv[4];
#pragma unroll
    for (int j = 0; j < 4; j++) {
        int c = 4 * lane + j;
        a2v[j] = g_a2[c]; c2v[j] = g_c2[c]; wv[j] = Ws2[c];
    }
    float bsv = bs2[0];

    int rbase = warp * 32;
    for (int rr = rbase; rr < rbase + 32; rr++) {
        if (rr >= nr) { if (lane == 0) es[rr] = 0.f; continue; }
        const bf16* z = g_Z1b + (size_t)(r0 + rr) * D + 4 * lane;
        unsigned u0 = *(const unsigned*)z;
        unsigned u1 = *(const unsigned*)(z + 2);
        float z0, z1, z2, z3;
        upk(u0, z0, z1); upk(u1, z2, z3);
        float p = fmaxf(a2v[0] * z0 + c2v[0], 0.f) * wv[0]
                + fmaxf(a2v[1] * z1 + c2v[1], 0.f) * wv[1]
                + fmaxf(a2v[2] * z2 + c2v[2], 0.f) * wv[2]
                + fmaxf(a2v[3] * z3 + c2v[3], 0.f) * wv[3];
#pragma unroll
        for (int o = 16; o > 0; o >>= 1) p += __shfl_xor_sync(0xffffffffu, p, o);
        if (lane == 0) es[rr] = expf(p + bsv);
    }
    __syncthreads();

    int c = tid & 127, half = tid >> 7;
    int rb = half * 128;
    float accn = 0.f, accd = 0.f;
    int cur = gid[rb];
    for (int i = 0; i < 128; i += 4) {
        float v[4], e[4];
#pragma unroll
        for (int j = 0; j < 4; j++) {
            int rr = rb + i + j;
            int r = r0 + rr;
            v[j] = (r < N) ? __bfloat162float(g_hfb[(size_t)r * D + c]) : 0.f;
            e[j] = es[rr];
        }
#pragma unroll
        for (int j = 0; j < 4; j++) {
            int rr = rb + i + j;
            int g = gid[rr];
            if (g != cur) {
                atomicAdd(&g_num[cur * D + c], accn);
                if (c == 0) atomicAdd(&g_den[cur], accd);
                accn = 0.f; accd = 0.f; cur = g;
            }
            if (r0 + rr < N) { accn += e[j] * v[j]; accd += e[j]; }
        }
    }
    atomicAdd(&g_num[cur * D + c], accn);
    if (c == 0) atomicAdd(&g_den[cur], accd);
}

// ---------------- K6: final combine ----------------
__global__ void k_out(float* __restrict__ out, const float* __restrict__ mix) {
    int i = blockIdx.x * blockDim.x + threadIdx.x;
    if (i >= G * D) return;
    int g = i / D;
    float alpha = 1.f / (1.f + expf(-mix[0]));
    float den = g_den[g];
    float wf = (den > 0.f) ? (g_num[i] / den) : 0.f;
    out[i] = alpha * wf + (1.f - alpha) * g_gm[i];
}

// ---------------- launch ----------------
extern "C" void kernel_launch(void* const* d_in, const int* in_sizes, int n_in,
                              void* d_out, int out_size) {
    const float* h   = (const float*)d_in[0];
    const float* sub = (const float*)d_in[1];
    const int* batch = (const int*)d_in[2];
    const float* W1  = (const float*)d_in[3];
    const float* b1  = (const float*)d_in[4];
    const float* g1  = (const float*)d_in[5];
    const float* be1 = (const float*)d_in[6];
    const float* Wg  = (const float*)d_in[7];
    const float* bg  = (const float*)d_in[8];
    const float* Ws1 = (const float*)d_in[9];
    const float* bs1 = (const float*)d_in[10];
    const float* g2  = (const float*)d_in[11];
    const float* be2 = (const float*)d_in[12];
    const float* Ws2 = (const float*)d_in[13];
    const float* bs2 = (const float*)d_in[14];
    const float* mix = (const float*)d_in[15];
    float* out = (float*)d_out;

    int N = in_sizes[0] / D;
    if (N > NMAX) N = NMAX;

    const int SMEM_P1 = 2 * 128 * LDWB * 2 + 512;
    const int SMEM_K3 = (2 * 128 * LDH + 2 * 128 * LDWB) * 2 + 5 * D * 4 + 512;
    cudaFuncSetAttribute(k_pass1, cudaFuncAttributeMaxDynamicSharedMemorySize, SMEM_P1);
    cudaFuncSetAttribute(k_fused, cudaFuncAttributeMaxDynamicSharedMemorySize, SMEM_K3);

    int nb = (N + 127) / 128;
    int nb2 = (N + 255) / 256;
    k_zero<<<(G * D + 255) / 256, 256>>>();
    k_prep<<<(4 * D * S + 255) / 256, 256>>>(W1, Wg, Ws1);
    k_pass1<<<nb, NT, SMEM_P1>>>(h, sub, batch, b1, N);
    k_mid<<<(G * D + 255) / 256, 256>>>(g1, be1, 1.f / (float)N);
    k_fused<<<nb, NT, SMEM_K3>>>(batch, b1, bg, bs1, N);
    k_bnfin2<<<1, 128>>>(g2, be2, 1.f / (float)N);
    k_score<<<nb2, 256>>>(batch, Ws2, bs2, N);
    k_out<<<(G * D + 255) / 256, 256>>>(out, mix);
}

// round 9
// speedup vs baseline: 1.0562x; 1.0562x over previous
#include <cuda_runtime.h>
#include <cuda_bf16.h>
#include <math.h>

#define D 128
#define S 64
#define G 256
#define NMAX 400000

#define LDH 136    // bf16 stride, activation tiles: conflict-free (LDSM rows: 4r mod 32)
#define LDWB 72    // bf16 stride, [n][k] weight tiles + sub tile: conflict-free
#define NT 256

typedef __nv_bfloat16 bf16;

// ---------------- persistent device scratch (allocation-free) ----------------
__device__ bf16 g_hb[(size_t)NMAX * D];
__device__ bf16 g_subb[(size_t)NMAX * S];
__device__ bf16 g_W1b[D * S];          // [n=128][k=64] transposed
__device__ bf16 g_Wgb[4 * D * S];      // [ck][n][k]
__device__ bf16 g_Ws1b[4 * D * S];     // [ck][n][k]
__device__ bf16 g_hfb[(size_t)NMAX * D];   // h_fused bf16
__device__ bf16 g_Z1b[(size_t)NMAX * D];   // Z1 bf16
__device__ float g_hs[G * D];
__device__ float g_hss[G * D];
__device__ float g_cnt[G];
__device__ float g_bn1sum[D], g_bn1sq[D];
__device__ float g_bn2sum[D], g_bn2sq[D];
__device__ float g_a1[D], g_c1[D], g_a2[D], g_c2[D];
__device__ float g_gm[G * D], g_gisd[G * D];
__device__ float g_num[G * D];
__device__ float g_den[G];

extern __shared__ float dynsmem[];

// ---------------- helpers ----------------
__device__ __forceinline__ void cp16(void* dst_smem, const void* src) {
    unsigned a = (unsigned)__cvta_generic_to_shared(dst_smem);
    asm volatile("cp.async.cg.shared.global [%0], [%1], 16;\n" :: "r"(a), "l"(src));
}
__device__ __forceinline__ void cp_commit() { asm volatile("cp.async.commit_group;\n"); }
template <int NN> __device__ __forceinline__ void cp_wait() {
    asm volatile("cp.async.wait_group %0;\n" :: "n"(NN));
}

__device__ __forceinline__ unsigned smem_u32(const void* p) {
    return (unsigned)__cvta_generic_to_shared(p);
}

__device__ __forceinline__ unsigned pk(float lo, float hi) {
    unsigned r;
    asm("cvt.rn.bf16x2.f32 %0, %1, %2;" : "=r"(r) : "f"(hi), "f"(lo));
    return r;
}
__device__ __forceinline__ void upk(unsigned v, float& lo, float& hi) {
    lo = __uint_as_float(v << 16);
    hi = __uint_as_float(v & 0xffff0000u);
}

__device__ __forceinline__ void mma_bf16(float* d, const unsigned* a, unsigned b0, unsigned b1) {
    asm volatile(
        "mma.sync.aligned.m16n8k16.row.col.f32.bf16.bf16.f32 "
        "{%0,%1,%2,%3}, {%4,%5,%6,%7}, {%8,%9}, {%0,%1,%2,%3};\n"
        : "+f"(d[0]), "+f"(d[1]), "+f"(d[2]), "+f"(d[3])
        : "r"(a[0]), "r"(a[1]), "r"(a[2]), "r"(a[3]), "r"(b0), "r"(b1));
}

__device__ __forceinline__ void ldsm4(unsigned* r, unsigned addr) {
    asm volatile("ldmatrix.sync.aligned.m8n8.x4.shared.b16 {%0,%1,%2,%3}, [%4];"
        : "=r"(r[0]), "=r"(r[1]), "=r"(r[2]), "=r"(r[3]) : "r"(addr));
}
__device__ __forceinline__ void ldsm2(unsigned& r0, unsigned& r1, unsigned addr) {
    asm volatile("ldmatrix.sync.aligned.m8n8.x2.shared.b16 {%0,%1}, [%2];"
        : "=r"(r0), "=r"(r1) : "r"(addr));
}

// 64-deep K chunk via ldmatrix; warp computes 32(M)x64(N) of a 128x128 tile. 8 warps.
// sA: bf16 [.][lda]; sB: bf16 weight tile [n=128][k=64] stride LDWB.
__device__ __forceinline__ void mma_chunk(float (&acc)[2][8][4],
                                          const bf16* sA, int lda, int kcol0,
                                          const bf16* sB, int wm, int wn, int lane) {
    // A: row = wm*32 + mt*16 + (lane&15), koff = (lane>>4)*8
    unsigned aBase0 = smem_u32(sA + (wm * 32 + (lane & 15)) * lda + kcol0 + (lane >> 4) * 8);
    unsigned aBase1 = aBase0 + 16 * lda * 2;
    // B: n = wn*64 + nt*8 + (lane&7), koff = ((lane>>3)&1)*8 (lanes 0-15 used by x2)
    unsigned bBase = smem_u32(sB + (wn * 64 + (lane & 7)) * LDWB + ((lane >> 3) & 1) * 8);
#pragma unroll
    for (int ks = 0; ks < 4; ks++) {
        unsigned a0[4], a1[4];
        ldsm4(a0, aBase0 + ks * 32);
        ldsm4(a1, aBase1 + ks * 32);
#pragma unroll
        for (int nt = 0; nt < 8; nt++) {
            unsigned b0, b1;
            ldsm2(b0, b1, bBase + ks * 32 + nt * (8 * LDWB * 2));
            mma_bf16(acc[0][nt], a0, b0, b1);
            mma_bf16(acc[1][nt], a1, b0, b1);
        }
    }
}

__device__ __forceinline__ void load_wchunk(bf16* buf, const bf16* Wsrc, int tid) {
#pragma unroll
    for (int j = 0; j < 4; j++) {
        int idx = tid + j * NT;
        int n = idx >> 3, f = idx & 7;
        cp16(buf + n * LDWB + f * 8, Wsrc + n * 64 + f * 8);
    }
}

// ---------------- K0: zero accumulators ----------------
__global__ void k_zero() {
    int i = blockIdx.x * blockDim.x + threadIdx.x;
    if (i < G * D) { g_hs[i] = 0.f; g_hss[i] = 0.f; g_num[i] = 0.f; }
    if (i < G) { g_cnt[i] = 0.f; g_den[i] = 0.f; }
    if (i < D) { g_bn1sum[i] = 0.f; g_bn1sq[i] = 0.f; g_bn2sum[i] = 0.f; g_bn2sq[i] = 0.f; }
}

// ---------------- K-prep: weights -> bf16, transposed [n][k] chunks ----------------
__global__ void k_prep(const float* __restrict__ W1, const float* __restrict__ Wg,
                       const float* __restrict__ Ws1) {
    int i = blockIdx.x * blockDim.x + threadIdx.x;
    if (i < D * S) {
        int n = i / S, k = i % S;
        g_W1b[i] = __float2bfloat16(W1[k * D + n]);
    }
    if (i < 4 * D * S) {
        int ck = i / (D * S), rem = i % (D * S);
        int n = rem / S, kl = rem % S;
        g_Wgb[i] = __float2bfloat16(Wg[(ck * S + kl) * D + n]);
        g_Ws1b[i] = __float2bfloat16(Ws1[(ck * S + kl) * D + n]);
    }
}

// ---------------- K1: h stats + bf16 emit + BN1 stats (R7 two-loop structure) ----------------
__global__ __launch_bounds__(NT, 2) void k_pass1(const float* __restrict__ h,
                                                 const float* __restrict__ sub,
                                                 const int* __restrict__ batch,
                                                 const float* __restrict__ b1, int N) {
    bf16* Sb = (bf16*)dynsmem;                 // [128][LDWB]
    bf16* Wp = Sb + 128 * LDWB;                // [128][LDWB]
    int* gid = (int*)(Wp + 128 * LDWB);        // [128]
    int tid = threadIdx.x, lane = tid & 31, warp = tid >> 5;
    int wm = warp >> 1, wn = warp & 1;
    int r0 = blockIdx.x * 128;

    load_wchunk(Wp, g_W1b, tid);
    cp_commit();
    if (tid < 128) gid[tid] = batch[min(r0 + tid, N - 1)];

    // sub: fp32 -> bf16 into Sb smem + g_subb global
    for (int i = tid; i < 128 * 32; i += NT) {
        int r = i >> 5, p2 = i & 31;
        int rr = min(r0 + r, N - 1);
        float2 v = *(const float2*)(sub + (size_t)rr * S + p2 * 2);
        unsigned w = pk(v.x, v.y);
        *(unsigned*)(Sb + r * LDWB + p2 * 2) = w;
        if (r0 + r < N) *(unsigned*)(g_subb + (size_t)(r0 + r) * S + p2 * 2) = w;
    }
    // h: fp32 -> bf16 global copy (streaming)
    for (int i = tid; i < 128 * 64; i += NT) {
        int r = i >> 6, p2 = i & 63;
        if (r0 + r < N) {
            float2 v = *(const float2*)(h + (size_t)(r0 + r) * D + p2 * 2);
            *(unsigned*)(g_hb + (size_t)(r0 + r) * D + p2 * 2) = pk(v.x, v.y);
        }
    }
    __syncthreads();

    // --- h segment stats (fp32, column-owner, run-length flush): 2 halves x 64 rows ---
    {
        int c = tid & 127, half = tid >> 7;
        int rbeg = half * 64;
        float s = 0.f, ss = 0.f, cf = 0.f;
        int cur = gid[rbeg];
        for (int i = 0; i < 64; i += 4) {
            float v[4];
#pragma unroll
            for (int j = 0; j < 4; j++) {
                int r = r0 + rbeg + i + j;
                v[j] = (r < N) ? h[(size_t)r * D + c] : 0.f;
            }
#pragma unroll
            for (int j = 0; j < 4; j++) {
                int rr = rbeg + i + j;
                int g = gid[rr];
                if (g != cur) {
                    atomicAdd(&g_hs[cur * D + c], s);
                    atomicAdd(&g_hss[cur * D + c], ss);
                    if (c == 0) atomicAdd(&g_cnt[cur], cf);
                    s = 0.f; ss = 0.f; cf = 0.f; cur = g;
                }
                if (r0 + rr < N) { s += v[j]; ss += v[j] * v[j]; cf += 1.f; }
            }
        }
        atomicAdd(&g_hs[cur * D + c], s);
        atomicAdd(&g_hss[cur * D + c], ss);
        if (c == 0) atomicAdd(&g_cnt[cur], cf);
    }

    // --- BN1 stats via bf16 mma from accumulators ---
    cp_wait<0>();
    __syncthreads();

    float acc[2][8][4];
#pragma unroll
    for (int mt = 0; mt < 2; mt++)
#pragma unroll
        for (int nt = 0; nt < 8; nt++)
#pragma unroll
            for (int e = 0; e < 4; e++) acc[mt][nt][e] = 0.f;

    mma_chunk(acc, Sb, LDWB, 0, Wp, wm, wn, lane);

    int g4 = lane >> 2, t4 = lane & 3;
#pragma unroll
    for (int nt = 0; nt < 8; nt++)
#pragma unroll
        for (int par = 0; par < 2; par++) {
            int ccol = wn * 64 + nt * 8 + t4 * 2 + par;
            float bb = b1[ccol];
            float s1 = 0.f, s2 = 0.f;
#pragma unroll
            for (int mt = 0; mt < 2; mt++)
#pragma unroll
                for (int rh = 0; rh < 2; rh++) {
                    int r = r0 + wm * 32 + mt * 16 + g4 + rh * 8;
                    float val = acc[mt][nt][rh * 2 + par] + bb;
                    if (r < N) { s1 += val; s2 += val * val; }
                }
#pragma unroll
            for (int o = 4; o < 32; o <<= 1) {
                s1 += __shfl_xor_sync(0xffffffffu, s1, o);
                s2 += __shfl_xor_sync(0xffffffffu, s2, o);
            }
            if (g4 == 0) {
                atomicAdd(&g_bn1sum[ccol], s1);
                atomicAdd(&g_bn1sq[ccol], s2);
            }
        }
}

// ---------------- K2: graph stat finalize + BN1 finalize ----------------
__global__ void k_mid(const float* __restrict__ gam, const float* __restrict__ bet, float invN) {
    int i = blockIdx.x * blockDim.x + threadIdx.x;
    if (i < G * D) {
        int g = i / D;
        float cnt = fmaxf(g_cnt[g], 1.f);
        float m = g_hs[i] / cnt;
        float v = g_hss[i] / cnt - m * m;
        float sd = sqrtf(fmaxf(v, 1e-8f));
        g_gm[i] = m;
        g_gisd[i] = 1.f / (sd + 1e-8f);
    }
    if (blockIdx.x == 0 && threadIdx.x < D) {
        int c = threadIdx.x;
        float mu = g_bn1sum[c] * invN;
        float var = g_bn1sq[c] * invN - mu * mu;
        float inv = rsqrtf(var + 1e-5f);
        g_a1[c] = gam[c] * inv;
        g_c1[c] = bet[c] - mu * gam[c] * inv;
    }
}

__global__ void k_bnfin2(const float* __restrict__ gam, const float* __restrict__ bet, float invN) {
    int i = threadIdx.x;
    float mu = g_bn2sum[i] * invN;
    float var = g_bn2sq[i] * invN - mu * mu;
    float inv = rsqrtf(var + 1e-5f);
    g_a2[i] = gam[i] * inv;
    g_c2[i] = bet[i] - mu * gam[i] * inv;
}

// ---------------- K3: big fused pass (bf16 tiles, ldmatrix, 2 CTAs/SM) ----------------
__global__ __launch_bounds__(NT, 2) void k_fused(
    const int* __restrict__ batch,
    const float* __restrict__ b1, const float* __restrict__ bg,
    const float* __restrict__ bs1, int N) {
    bf16* Hb = (bf16*)dynsmem;                 // [128][LDH]  h -> h_dev
    bf16* Eb = Hb + 128 * LDH;                 // [128][LDH]  sub_e -> h_fused
    bf16* Wq = Eb + 128 * LDH;                 // [128][LDWB] sub, then pong
    bf16* Wp = Wq + 128 * LDWB;                // [128][LDWB] W1, then ping
    float* pa1 = (float*)(Wp + 128 * LDWB);
    float* pc1 = pa1 + D;
    float* pb1 = pc1 + D;
    float* pbg = pb1 + D;
    float* pbs1 = pbg + D;
    int* gid = (int*)(pbs1 + D);               // [128]

    int tid = threadIdx.x, lane = tid & 31, warp = tid >> 5;
    int wm = warp >> 1, wn = warp & 1;
    int g4 = lane >> 2, t4 = lane & 3;
    int r0 = blockIdx.x * 128;

#pragma unroll
    for (int j = 0; j < 4; j++) {
        int idx = tid + j * NT;
        int r = idx >> 3, f = idx & 7;
        int rr = min(r0 + r, N - 1);
        cp16(Wq + r * LDWB + f * 8, g_subb + (size_t)rr * S + f * 8);
    }
    load_wchunk(Wp, g_W1b, tid);
    cp_commit();
#pragma unroll
    for (int j = 0; j < 8; j++) {
        int idx = tid + j * NT;
        int r = idx >> 4, f = idx & 15;
        int rr = min(r0 + r, N - 1);
        cp16(Hb + r * LDH + f * 8, g_hb + (size_t)rr * D + f * 8);
    }
    cp_commit();

    if (tid < 128) {
        pa1[tid] = g_a1[tid]; pc1[tid] = g_c1[tid]; pb1[tid] = b1[tid];
        pbg[tid] = bg[tid]; pbs1[tid] = bs1[tid];
        gid[tid] = batch[min(r0 + tid, N - 1)];
    }

    float acc[2][8][4];
#pragma unroll
    for (int mt = 0; mt < 2; mt++)
#pragma unroll
        for (int nt = 0; nt < 8; nt++)
#pragma unroll
            for (int e = 0; e < 4; e++) acc[mt][nt][e] = 0.f;

    // ---- mma1: X1 = sub @ W1 ----
    cp_wait<1>();
    __syncthreads();
    mma_chunk(acc, Wq, LDWB, 0, Wp, wm, wn, lane);

    // sub_e epilogue -> Eb
#pragma unroll
    for (int mt = 0; mt < 2; mt++)
#pragma unroll
        for (int nt = 0; nt < 8; nt++)
#pragma unroll
            for (int rh = 0; rh < 2; rh++) {
                int r = wm * 32 + mt * 16 + g4 + rh * 8;
                int c = wn * 64 + nt * 8 + 2 * t4;
                float x0 = acc[mt][nt][rh * 2 + 0] + pb1[c];
                float x1 = acc[mt][nt][rh * 2 + 1] + pb1[c + 1];
                float e0 = fmaxf(pa1[c] * x0 + pc1[c], 0.f);
                float e1 = fmaxf(pa1[c + 1] * x1 + pc1[c + 1], 0.f);
                *(unsigned*)(Eb + r * LDH + c) = pk(e0, e1);
                acc[mt][nt][rh * 2 + 0] = 0.f;
                acc[mt][nt][rh * 2 + 1] = 0.f;
            }
    __syncthreads();

    const bf16* Wtab[8] = { g_Wgb, g_Wgb + 8192, g_Wgb + 16384, g_Wgb + 24576,
                            g_Ws1b, g_Ws1b + 8192, g_Ws1b + 16384, g_Ws1b + 24576 };
    load_wchunk(Wp, Wtab[0], tid); cp_commit();
    load_wchunk(Wq, Wtab[1], tid); cp_commit();

#pragma unroll 1
    for (int k = 0; k < 8; k++) {
        if (k < 6) cp_wait<1>(); else cp_wait<0>();
        __syncthreads();
        bf16* buf = (k & 1) ? Wq : Wp;
        const bf16* A = (k < 2) ? Hb : (k < 6) ? Eb : Hb;
        mma_chunk(acc, A, LDH, (k & 1) * 64, buf, wm, wn, lane);
        __syncthreads();
        if (k + 2 < 8) { load_wchunk(buf, Wtab[k + 2], tid); cp_commit(); }

        if (k == 3) {
            // gate epilogue: h_fused = h + sigmoid(acc+bg)*sub_e  (bf16 out)
#pragma unroll
            for (int mt = 0; mt < 2; mt++)
#pragma unroll
                for (int nt = 0; nt < 8; nt++)
#pragma unroll
                    for (int rh = 0; rh < 2; rh++) {
                        int r = wm * 32 + mt * 16 + g4 + rh * 8;
                        int c = wn * 64 + nt * 8 + 2 * t4;
                        float gx0 = acc[mt][nt][rh * 2 + 0] + pbg[c];
                        float gx1 = acc[mt][nt][rh * 2 + 1] + pbg[c + 1];
                        float gt0 = 1.f / (1.f + expf(-gx0));
                        float gt1 = 1.f / (1.f + expf(-gx1));
                        float h0, h1, s0, s1;
                        upk(*(const unsigned*)(Hb + r * LDH + c), h0, h1);
                        upk(*(const unsigned*)(Eb + r * LDH + c), s0, s1);
                        unsigned w = pk(h0 + gt0 * s0, h1 + gt1 * s1);
                        if (r0 + r < N)
                            *(unsigned*)(g_hfb + (size_t)(r0 + r) * D + c) = w;
                        *(unsigned*)(Eb + r * LDH + c) = w;
                        acc[mt][nt][rh * 2 + 0] = 0.f;
                        acc[mt][nt][rh * 2 + 1] = 0.f;
                    }
            __syncthreads();
            // Hb: h -> h_dev
            for (int i = tid; i < 128 * 64; i += NT) {
                int r = i >> 6, c = (i & 63) * 2;
                int g = gid[r];
                float h0, h1;
                upk(*(const unsigned*)(Hb + r * LDH + c), h0, h1);
                float2 m2 = *(const float2*)(g_gm + g * D + c);
                float2 i2 = *(const float2*)(g_gisd + g * D + c);
                *(unsigned*)(Hb + r * LDH + c) = pk((h0 - m2.x) * i2.x, (h1 - m2.y) * i2.y);
            }
            __syncthreads();
        }
    }

    // mma3 epilogue: Z1 bf16 to global + BN2 stats from fp32 accumulators
#pragma unroll
    for (int mt = 0; mt < 2; mt++)
#pragma unroll
        for (int nt = 0; nt < 8; nt++)
#pragma unroll
            for (int rh = 0; rh < 2; rh++) {
                int r = wm * 32 + mt * 16 + g4 + rh * 8;
                int c = wn * 64 + nt * 8 + 2 * t4;
                if (r0 + r < N) {
                    float z0 = acc[mt][nt][rh * 2 + 0] + pbs1[c];
                    float z1 = acc[mt][nt][rh * 2 + 1] + pbs1[c + 1];
                    *(unsigned*)(g_Z1b + (size_t)(r0 + r) * D + c) = pk(z0, z1);
                }
            }
#pragma unroll
    for (int nt = 0; nt < 8; nt++)
#pragma unroll
        for (int par = 0; par < 2; par++) {
            int ccol = wn * 64 + nt * 8 + 2 * t4 + par;
            float bb = pbs1[ccol];
            float s1 = 0.f, s2 = 0.f;
#pragma unroll
            for (int mt = 0; mt < 2; mt++)
#pragma unroll
                for (int rh = 0; rh < 2; rh++) {
                    int r = r0 + wm * 32 + mt * 16 + g4 + rh * 8;
                    float val = acc[mt][nt][rh * 2 + par] + bb;
                    if (r < N) { s1 += val; s2 += val * val; }
                }
#pragma unroll
            for (int o = 4; o < 32; o <<= 1) {
                s1 += __shfl_xor_sync(0xffffffffu, s1, o);
                s2 += __shfl_xor_sync(0xffffffffu, s2, o);
            }
            if (g4 == 0) {
                atomicAdd(&g_bn2sum[ccol], s1);
                atomicAdd(&g_bn2sq[ccol], s2);
            }
        }
}

// ---------------- K5: logits + exp + weighted segment sums (bf16 inputs) ----------------
__global__ __launch_bounds__(256) void k_score(const int* __restrict__ batch,
                                               const float* __restrict__ Ws2,
                                               const float* __restrict__ bs2, int N) {
    __shared__ float es[256];
    __shared__ int gid[256];
    int tid = threadIdx.x, lane = tid & 31, warp = tid >> 5;
    int r0 = blockIdx.x * 256;
    int nr = min(256, N - r0);
    gid[tid] = batch[min(r0 + min(tid, nr - 1), N - 1)];

    float a2v[4], c2v[4], wv[4];
#pragma unroll
    for (int j = 0; j < 4; j++) {
        int c = 4 * lane + j;
        a2v[j] = g_a2[c]; c2v[j] = g_c2[c]; wv[j] = Ws2[c];
    }
    float bsv = bs2[0];

    int rbase = warp * 32;
    for (int rr = rbase; rr < rbase + 32; rr++) {
        if (rr >= nr) { if (lane == 0) es[rr] = 0.f; continue; }
        const bf16* z = g_Z1b + (size_t)(r0 + rr) * D + 4 * lane;
        unsigned u0 = *(const unsigned*)z;
        unsigned u1 = *(const unsigned*)(z + 2);
        float z0, z1, z2, z3;
        upk(u0, z0, z1); upk(u1, z2, z3);
        float p = fmaxf(a2v[0] * z0 + c2v[0], 0.f) * wv[0]
                + fmaxf(a2v[1] * z1 + c2v[1], 0.f) * wv[1]
                + fmaxf(a2v[2] * z2 + c2v[2], 0.f) * wv[2]
                + fmaxf(a2v[3] * z3 + c2v[3], 0.f) * wv[3];
#pragma unroll
        for (int o = 16; o > 0; o >>= 1) p += __shfl_xor_sync(0xffffffffu, p, o);
        if (lane == 0) es[rr] = expf(p + bsv);
    }
    __syncthreads();

    int c = tid & 127, half = tid >> 7;
    int rb = half * 128;
    float accn = 0.f, accd = 0.f;
    int cur = gid[rb];
    for (int i = 0; i < 128; i += 4) {
        float v[4], e[4];
#pragma unroll
        for (int j = 0; j < 4; j++) {
            int rr = rb + i + j;
            int r = r0 + rr;
            v[j] = (r < N) ? __bfloat162float(g_hfb[(size_t)r * D + c]) : 0.f;
            e[j] = es[rr];
        }
#pragma unroll
        for (int j = 0; j < 4; j++) {
            int rr = rb + i + j;
            int g = gid[rr];
            if (g != cur) {
                atomicAdd(&g_num[cur * D + c], accn);
                if (c == 0) atomicAdd(&g_den[cur], accd);
                accn = 0.f; accd = 0.f; cur = g;
            }
            if (r0 + rr < N) { accn += e[j] * v[j]; accd += e[j]; }
        }
    }
    atomicAdd(&g_num[cur * D + c], accn);
    if (c == 0) atomicAdd(&g_den[cur], accd);
}

// ---------------- K6: final combine ----------------
__global__ void k_out(float* __restrict__ out, const float* __restrict__ mix) {
    int i = blockIdx.x * blockDim.x + threadIdx.x;
    if (i >= G * D) return;
    int g = i / D;
    float alpha = 1.f / (1.f + expf(-mix[0]));
    float den = g_den[g];
    float wf = (den > 0.f) ? (g_num[i] / den) : 0.f;
    out[i] = alpha * wf + (1.f - alpha) * g_gm[i];
}

// ---------------- launch ----------------
extern "C" void kernel_launch(void* const* d_in, const int* in_sizes, int n_in,
                              void* d_out, int out_size) {
    const float* h   = (const float*)d_in[0];
    const float* sub = (const float*)d_in[1];
    const int* batch = (const int*)d_in[2];
    const float* W1  = (const float*)d_in[3];
    const float* b1  = (const float*)d_in[4];
    const float* g1  = (const float*)d_in[5];
    const float* be1 = (const float*)d_in[6];
    const float* Wg  = (const float*)d_in[7];
    const float* bg  = (const float*)d_in[8];
    const float* Ws1 = (const float*)d_in[9];
    const float* bs1 = (const float*)d_in[10];
    const float* g2  = (const float*)d_in[11];
    const float* be2 = (const float*)d_in[12];
    const float* Ws2 = (const float*)d_in[13];
    const float* bs2 = (const float*)d_in[14];
    const float* mix = (const float*)d_in[15];
    float* out = (float*)d_out;

    int N = in_sizes[0] / D;
    if (N > NMAX) N = NMAX;

    const int SMEM_P1 = 2 * 128 * LDWB * 2 + 512;
    const int SMEM_K3 = (2 * 128 * LDH + 2 * 128 * LDWB) * 2 + 5 * D * 4 + 512;
    cudaFuncSetAttribute(k_pass1, cudaFuncAttributeMaxDynamicSharedMemorySize, SMEM_P1);
    cudaFuncSetAttribute(k_fused, cudaFuncAttributeMaxDynamicSharedMemorySize, SMEM_K3);

    int nb = (N + 127) / 128;
    int nb2 = (N + 255) / 256;
    k_zero<<<(G * D + 255) / 256, 256>>>();
    k_prep<<<(4 * D * S + 255) / 256, 256>>>(W1, Wg, Ws1);
    k_pass1<<<nb, NT, SMEM_P1>>>(h, sub, batch, b1, N);
    k_mid<<<(G * D + 255) / 256, 256>>>(g1, be1, 1.f / (float)N);
    k_fused<<<nb, NT, SMEM_K3>>>(batch, b1, bg, bs1, N);
    k_bnfin2<<<1, 128>>>(g2, be2, 1.f / (float)N);
    k_score<<<nb2, 256>>>(batch, Ws2, bs2, N);
    k_out<<<(G * D + 255) / 256, 256>>>(out, mix);
}

// round 10
// speedup vs baseline: 1.0642x; 1.0076x over previous
#include <cuda_runtime.h>
#include <cuda_bf16.h>
#include <math.h>

#define D 128
#define S 64
#define G 256
#define NMAX 400000

#define LDH 136    // bf16 stride, activation tiles: conflict-free
#define LDWB 72    // bf16 stride, [n][k] weight tiles + sub tile: conflict-free
#define NT 256

typedef __nv_bfloat16 bf16;

// ---------------- persistent device scratch (allocation-free) ----------------
__device__ bf16 g_hb[(size_t)NMAX * D];
__device__ bf16 g_subb[(size_t)NMAX * S];
__device__ bf16 g_W1b[D * S];          // [n=128][k=64] transposed
__device__ bf16 g_Wgb[4 * D * S];      // [ck][n][k]
__device__ bf16 g_Ws1b[4 * D * S];     // [ck][n][k]
__device__ bf16 g_hfb[(size_t)NMAX * D];   // h_fused bf16
__device__ bf16 g_Z1b[(size_t)NMAX * D];   // Z1 bf16
__device__ float g_hs[G * D];
__device__ float g_hss[G * D];
__device__ float g_cnt[G];
__device__ float g_bn1sum[D], g_bn1sq[D];
__device__ float g_bn2sum[D], g_bn2sq[D];
__device__ float g_a1[D], g_c1[D];
__device__ float g_gm[G * D], g_gisd[G * D];
__device__ float g_num[G * D];
__device__ float g_den[G];

extern __shared__ float dynsmem[];

// ---------------- helpers ----------------
__device__ __forceinline__ void cp16(void* dst_smem, const void* src) {
    unsigned a = (unsigned)__cvta_generic_to_shared(dst_smem);
    asm volatile("cp.async.cg.shared.global [%0], [%1], 16;\n" :: "r"(a), "l"(src));
}
__device__ __forceinline__ void cp_commit() { asm volatile("cp.async.commit_group;\n"); }
template <int NN> __device__ __forceinline__ void cp_wait() {
    asm volatile("cp.async.wait_group %0;\n" :: "n"(NN));
}

__device__ __forceinline__ unsigned smem_u32(const void* p) {
    return (unsigned)__cvta_generic_to_shared(p);
}

__device__ __forceinline__ unsigned pk(float lo, float hi) {
    unsigned r;
    asm("cvt.rn.bf16x2.f32 %0, %1, %2;" : "=r"(r) : "f"(hi), "f"(lo));
    return r;
}
__device__ __forceinline__ void upk(unsigned v, float& lo, float& hi) {
    lo = __uint_as_float(v << 16);
    hi = __uint_as_float(v & 0xffff0000u);
}

__device__ __forceinline__ void mma_bf16(float* d, const unsigned* a, unsigned b0, unsigned b1) {
    asm volatile(
        "mma.sync.aligned.m16n8k16.row.col.f32.bf16.bf16.f32 "
        "{%0,%1,%2,%3}, {%4,%5,%6,%7}, {%8,%9}, {%0,%1,%2,%3};\n"
        : "+f"(d[0]), "+f"(d[1]), "+f"(d[2]), "+f"(d[3])
        : "r"(a[0]), "r"(a[1]), "r"(a[2]), "r"(a[3]), "r"(b0), "r"(b1));
}

__device__ __forceinline__ void ldsm4(unsigned* r, unsigned addr) {
    asm volatile("ldmatrix.sync.aligned.m8n8.x4.shared.b16 {%0,%1,%2,%3}, [%4];"
        : "=r"(r[0]), "=r"(r[1]), "=r"(r[2]), "=r"(r[3]) : "r"(addr));
}
__device__ __forceinline__ void ldsm2(unsigned& r0, unsigned& r1, unsigned addr) {
    asm volatile("ldmatrix.sync.aligned.m8n8.x2.shared.b16 {%0,%1}, [%2];"
        : "=r"(r0), "=r"(r1) : "r"(addr));
}

// 64-deep K chunk via ldmatrix; warp computes 32(M)x64(N) of a 128x128 tile. 8 warps.
__device__ __forceinline__ void mma_chunk(float (&acc)[2][8][4],
                                          const bf16* sA, int lda, int kcol0,
                                          const bf16* sB, int wm, int wn, int lane) {
    unsigned aBase0 = smem_u32(sA + (wm * 32 + (lane & 15)) * lda + kcol0 + (lane >> 4) * 8);
    unsigned aBase1 = aBase0 + 16 * lda * 2;
    unsigned bBase = smem_u32(sB + (wn * 64 + (lane & 7)) * LDWB + ((lane >> 3) & 1) * 8);
#pragma unroll
    for (int ks = 0; ks < 4; ks++) {
        unsigned a0[4], a1[4];
        ldsm4(a0, aBase0 + ks * 32);
        ldsm4(a1, aBase1 + ks * 32);
#pragma unroll
        for (int nt = 0; nt < 8; nt++) {
            unsigned b0, b1;
            ldsm2(b0, b1, bBase + ks * 32 + nt * (8 * LDWB * 2));
            mma_bf16(acc[0][nt], a0, b0, b1);
            mma_bf16(acc[1][nt], a1, b0, b1);
        }
    }
}

__device__ __forceinline__ void load_wchunk(bf16* buf, const bf16* Wsrc, int tid) {
#pragma unroll
    for (int j = 0; j < 4; j++) {
        int idx = tid + j * NT;
        int n = idx >> 3, f = idx & 7;
        cp16(buf + n * LDWB + f * 8, Wsrc + n * 64 + f * 8);
    }
}

// ---------------- K0: zero accumulators + weight prep (merged) ----------------
__global__ void k_init(const float* __restrict__ W1, const float* __restrict__ Wg,
                       const float* __restrict__ Ws1) {
    int i = blockIdx.x * blockDim.x + threadIdx.x;
    if (i < G * D) { g_hs[i] = 0.f; g_hss[i] = 0.f; g_num[i] = 0.f; }
    if (i < G) { g_cnt[i] = 0.f; g_den[i] = 0.f; }
    if (i < D) { g_bn1sum[i] = 0.f; g_bn1sq[i] = 0.f; g_bn2sum[i] = 0.f; g_bn2sq[i] = 0.f; }
    if (i < D * S) {
        int n = i / S, k = i % S;
        g_W1b[i] = __float2bfloat16(W1[k * D + n]);
    }
    if (i < 4 * D * S) {
        int ck = i / (D * S), rem = i % (D * S);
        int n = rem / S, kl = rem % S;
        g_Wgb[i] = __float2bfloat16(Wg[(ck * S + kl) * D + n]);
        g_Ws1b[i] = __float2bfloat16(Ws1[(ck * S + kl) * D + n]);
    }
}

// ---------------- K1: single-read h (stats + bf16 emit) + sub emit + BN1 stats ----------------
__global__ __launch_bounds__(NT, 2) void k_pass1(const float* __restrict__ h,
                                                 const float* __restrict__ sub,
                                                 const int* __restrict__ batch,
                                                 const float* __restrict__ b1, int N) {
    bf16* Sb = (bf16*)dynsmem;                 // [128][LDWB]
    bf16* Wp = Sb + 128 * LDWB;                // [128][LDWB]
    int* gid = (int*)(Wp + 128 * LDWB);        // [128]
    int tid = threadIdx.x, lane = tid & 31, warp = tid >> 5;
    int wm = warp >> 1, wn = warp & 1;
    int r0 = blockIdx.x * 128;

    load_wchunk(Wp, g_W1b, tid);
    cp_commit();
    if (tid < 128) gid[tid] = batch[min(r0 + tid, N - 1)];

    // sub: fp32 -> bf16 into Sb smem + g_subb global
    for (int i = tid; i < 128 * 32; i += NT) {
        int r = i >> 5, p2 = i & 31;
        int rr = min(r0 + r, N - 1);
        float2 v = *(const float2*)(sub + (size_t)rr * S + p2 * 2);
        unsigned w = pk(v.x, v.y);
        *(unsigned*)(Sb + r * LDWB + p2 * 2) = w;
        if (r0 + r < N) *(unsigned*)(g_subb + (size_t)(r0 + r) * S + p2 * 2) = w;
    }
    __syncthreads();   // gid visible

    // --- h: ONE fp32 read -> bf16 emit + segment stats ---
    // thread owns column-pair c=2*(tid&63), contiguous rows q*32..q*32+31, batch-4 loads
    {
        int p2 = tid & 63;
        int c = p2 * 2;
        int q = tid >> 6;                      // 0..3
        int rbeg = q * 32;
        float s0 = 0.f, s1 = 0.f, q0 = 0.f, q1 = 0.f, cf = 0.f;
        int cur = gid[rbeg];
        for (int i = 0; i < 32; i += 4) {
            float2 v[4];
#pragma unroll
            for (int j = 0; j < 4; j++) {
                int rg = r0 + rbeg + i + j;
                v[j] = (rg < N) ? *(const float2*)(h + (size_t)rg * D + c)
                                : make_float2(0.f, 0.f);
            }
#pragma unroll
            for (int j = 0; j < 4; j++) {
                int rr = rbeg + i + j;
                int rg = r0 + rr;
                if (rg < N)
                    *(unsigned*)(g_hb + (size_t)rg * D + c) = pk(v[j].x, v[j].y);
                int g = gid[rr];
                if (g != cur) {
                    atomicAdd(&g_hs[cur * D + c], s0);
                    atomicAdd(&g_hs[cur * D + c + 1], s1);
                    atomicAdd(&g_hss[cur * D + c], q0);
                    atomicAdd(&g_hss[cur * D + c + 1], q1);
                    if (p2 == 0) atomicAdd(&g_cnt[cur], cf);
                    s0 = s1 = q0 = q1 = cf = 0.f;
                    cur = g;
                }
                if (rg < N) {
                    s0 += v[j].x; s1 += v[j].y;
                    q0 += v[j].x * v[j].x; q1 += v[j].y * v[j].y;
                    cf += 1.f;
                }
            }
        }
        atomicAdd(&g_hs[cur * D + c], s0);
        atomicAdd(&g_hs[cur * D + c + 1], s1);
        atomicAdd(&g_hss[cur * D + c], q0);
        atomicAdd(&g_hss[cur * D + c + 1], q1);
        if (p2 == 0) atomicAdd(&g_cnt[cur], cf);
    }

    // --- BN1 stats via bf16 mma from accumulators ---
    cp_wait<0>();
    __syncthreads();

    float acc[2][8][4];
#pragma unroll
    for (int mt = 0; mt < 2; mt++)
#pragma unroll
        for (int nt = 0; nt < 8; nt++)
#pragma unroll
            for (int e = 0; e < 4; e++) acc[mt][nt][e] = 0.f;

    mma_chunk(acc, Sb, LDWB, 0, Wp, wm, wn, lane);

    int g4 = lane >> 2, t4 = lane & 3;
#pragma unroll
    for (int nt = 0; nt < 8; nt++)
#pragma unroll
        for (int par = 0; par < 2; par++) {
            int ccol = wn * 64 + nt * 8 + t4 * 2 + par;
            float bb = b1[ccol];
            float s1 = 0.f, s2 = 0.f;
#pragma unroll
            for (int mt = 0; mt < 2; mt++)
#pragma unroll
                for (int rh = 0; rh < 2; rh++) {
                    int r = r0 + wm * 32 + mt * 16 + g4 + rh * 8;
                    float val = acc[mt][nt][rh * 2 + par] + bb;
                    if (r < N) { s1 += val; s2 += val * val; }
                }
#pragma unroll
            for (int o = 4; o < 32; o <<= 1) {
                s1 += __shfl_xor_sync(0xffffffffu, s1, o);
                s2 += __shfl_xor_sync(0xffffffffu, s2, o);
            }
            if (g4 == 0) {
                atomicAdd(&g_bn1sum[ccol], s1);
                atomicAdd(&g_bn1sq[ccol], s2);
            }
        }
}

// ---------------- K2: graph stat finalize + BN1 finalize ----------------
__global__ void k_mid(const float* __restrict__ gam, const float* __restrict__ bet, float invN) {
    int i = blockIdx.x * blockDim.x + threadIdx.x;
    if (i < G * D) {
        int g = i / D;
        float cnt = fmaxf(g_cnt[g], 1.f);
        float m = g_hs[i] / cnt;
        float v = g_hss[i] / cnt - m * m;
        float sd = sqrtf(fmaxf(v, 1e-8f));
        g_gm[i] = m;
        g_gisd[i] = 1.f / (sd + 1e-8f);
    }
    if (blockIdx.x == 0 && threadIdx.x < D) {
        int c = threadIdx.x;
        float mu = g_bn1sum[c] * invN;
        float var = g_bn1sq[c] * invN - mu * mu;
        float inv = rsqrtf(var + 1e-5f);
        g_a1[c] = gam[c] * inv;
        g_c1[c] = bet[c] - mu * gam[c] * inv;
    }
}

// ---------------- K3: big fused pass (bf16 tiles, ldmatrix, 2 CTAs/SM) ----------------
__global__ __launch_bounds__(NT, 2) void k_fused(
    const int* __restrict__ batch,
    const float* __restrict__ b1, const float* __restrict__ bg,
    const float* __restrict__ bs1, int N) {
    bf16* Hb = (bf16*)dynsmem;                 // [128][LDH]  h -> h_dev
    bf16* Eb = Hb + 128 * LDH;                 // [128][LDH]  sub_e -> h_fused
    bf16* Wq = Eb + 128 * LDH;                 // [128][LDWB] sub, then pong
    bf16* Wp = Wq + 128 * LDWB;                // [128][LDWB] W1, then ping
    float* pa1 = (float*)(Wp + 128 * LDWB);
    float* pc1 = pa1 + D;
    float* pb1 = pc1 + D;
    float* pbg = pb1 + D;
    float* pbs1 = pbg + D;
    int* gid = (int*)(pbs1 + D);               // [128]

    int tid = threadIdx.x, lane = tid & 31, warp = tid >> 5;
    int wm = warp >> 1, wn = warp & 1;
    int g4 = lane >> 2, t4 = lane & 3;
    int r0 = blockIdx.x * 128;

#pragma unroll
    for (int j = 0; j < 4; j++) {
        int idx = tid + j * NT;
        int r = idx >> 3, f = idx & 7;
        int rr = min(r0 + r, N - 1);
        cp16(Wq + r * LDWB + f * 8, g_subb + (size_t)rr * S + f * 8);
    }
    load_wchunk(Wp, g_W1b, tid);
    cp_commit();
#pragma unroll
    for (int j = 0; j < 8; j++) {
        int idx = tid + j * NT;
        int r = idx >> 4, f = idx & 15;
        int rr = min(r0 + r, N - 1);
        cp16(Hb + r * LDH + f * 8, g_hb + (size_t)rr * D + f * 8);
    }
    cp_commit();

    if (tid < 128) {
        pa1[tid] = g_a1[tid]; pc1[tid] = g_c1[tid]; pb1[tid] = b1[tid];
        pbg[tid] = bg[tid]; pbs1[tid] = bs1[tid];
        gid[tid] = batch[min(r0 + tid, N - 1)];
    }

    float acc[2][8][4];
#pragma unroll
    for (int mt = 0; mt < 2; mt++)
#pragma unroll
        for (int nt = 0; nt < 8; nt++)
#pragma unroll
            for (int e = 0; e < 4; e++) acc[mt][nt][e] = 0.f;

    // ---- mma1: X1 = sub @ W1 ----
    cp_wait<1>();
    __syncthreads();
    mma_chunk(acc, Wq, LDWB, 0, Wp, wm, wn, lane);

    // sub_e epilogue -> Eb
#pragma unroll
    for (int mt = 0; mt < 2; mt++)
#pragma unroll
        for (int nt = 0; nt < 8; nt++)
#pragma unroll
            for (int rh = 0; rh < 2; rh++) {
                int r = wm * 32 + mt * 16 + g4 + rh * 8;
                int c = wn * 64 + nt * 8 + 2 * t4;
                float x0 = acc[mt][nt][rh * 2 + 0] + pb1[c];
                float x1 = acc[mt][nt][rh * 2 + 1] + pb1[c + 1];
                float e0 = fmaxf(pa1[c] * x0 + pc1[c], 0.f);
                float e1 = fmaxf(pa1[c + 1] * x1 + pc1[c + 1], 0.f);
                *(unsigned*)(Eb + r * LDH + c) = pk(e0, e1);
                acc[mt][nt][rh * 2 + 0] = 0.f;
                acc[mt][nt][rh * 2 + 1] = 0.f;
            }
    __syncthreads();

    const bf16* Wtab[8] = { g_Wgb, g_Wgb + 8192, g_Wgb + 16384, g_Wgb + 24576,
                            g_Ws1b, g_Ws1b + 8192, g_Ws1b + 16384, g_Ws1b + 24576 };
    load_wchunk(Wp, Wtab[0], tid); cp_commit();
    load_wchunk(Wq, Wtab[1], tid); cp_commit();

#pragma unroll 1
    for (int k = 0; k < 8; k++) {
        if (k < 6) cp_wait<1>(); else cp_wait<0>();
        __syncthreads();
        bf16* buf = (k & 1) ? Wq : Wp;
        const bf16* A = (k < 2) ? Hb : (k < 6) ? Eb : Hb;
        mma_chunk(acc, A, LDH, (k & 1) * 64, buf, wm, wn, lane);
        __syncthreads();
        if (k + 2 < 8) { load_wchunk(buf, Wtab[k + 2], tid); cp_commit(); }

        if (k == 3) {
            // merged gate + h_dev epilogue: each fragment position owned by one thread
#pragma unroll
            for (int mt = 0; mt < 2; mt++)
#pragma unroll
                for (int nt = 0; nt < 8; nt++)
#pragma unroll
                    for (int rh = 0; rh < 2; rh++) {
                        int r = wm * 32 + mt * 16 + g4 + rh * 8;
                        int c = wn * 64 + nt * 8 + 2 * t4;
                        float gx0 = acc[mt][nt][rh * 2 + 0] + pbg[c];
                        float gx1 = acc[mt][nt][rh * 2 + 1] + pbg[c + 1];
                        float gt0 = 1.f / (1.f + expf(-gx0));
                        float gt1 = 1.f / (1.f + expf(-gx1));
                        float h0, h1, s0, s1;
                        upk(*(const unsigned*)(Hb + r * LDH + c), h0, h1);
                        upk(*(const unsigned*)(Eb + r * LDH + c), s0, s1);
                        unsigned w = pk(h0 + gt0 * s0, h1 + gt1 * s1);
                        if (r0 + r < N)
                            *(unsigned*)(g_hfb + (size_t)(r0 + r) * D + c) = w;
                        *(unsigned*)(Eb + r * LDH + c) = w;
                        // h_dev in place
                        int g = gid[r];
                        float2 m2 = *(const float2*)(g_gm + g * D + c);
                        float2 i2 = *(const float2*)(g_gisd + g * D + c);
                        *(unsigned*)(Hb + r * LDH + c) =
                            pk((h0 - m2.x) * i2.x, (h1 - m2.y) * i2.y);
                        acc[mt][nt][rh * 2 + 0] = 0.f;
                        acc[mt][nt][rh * 2 + 1] = 0.f;
                    }
            __syncthreads();
        }
    }

    // mma3 epilogue: Z1 bf16 to global + BN2 stats from fp32 accumulators
#pragma unroll
    for (int mt = 0; mt < 2; mt++)
#pragma unroll
        for (int nt = 0; nt < 8; nt++)
#pragma unroll
            for (int rh = 0; rh < 2; rh++) {
                int r = wm * 32 + mt * 16 + g4 + rh * 8;
                int c = wn * 64 + nt * 8 + 2 * t4;
                if (r0 + r < N) {
                    float z0 = acc[mt][nt][rh * 2 + 0] + pbs1[c];
                    float z1 = acc[mt][nt][rh * 2 + 1] + pbs1[c + 1];
                    *(unsigned*)(g_Z1b + (size_t)(r0 + r) * D + c) = pk(z0, z1);
                }
            }
#pragma unroll
    for (int nt = 0; nt < 8; nt++)
#pragma unroll
        for (int par = 0; par < 2; par++) {
            int ccol = wn * 64 + nt * 8 + 2 * t4 + par;
            float bb = pbs1[ccol];
            float s1 = 0.f, s2 = 0.f;
#pragma unroll
            for (int mt = 0; mt < 2; mt++)
#pragma unroll
                for (int rh = 0; rh < 2; rh++) {
                    int r = r0 + wm * 32 + mt * 16 + g4 + rh * 8;
                    float val = acc[mt][nt][rh * 2 + par] + bb;
                    if (r < N) { s1 += val; s2 += val * val; }
                }
#pragma unroll
            for (int o = 4; o < 32; o <<= 1) {
                s1 += __shfl_xor_sync(0xffffffffu, s1, o);
                s2 += __shfl_xor_sync(0xffffffffu, s2, o);
            }
            if (g4 == 0) {
                atomicAdd(&g_bn2sum[ccol], s1);
                atomicAdd(&g_bn2sq[ccol], s2);
            }
        }
}

// ---------------- K5: BN2 finalize (per-block) + logits + exp + weighted segment sums ----------------
__global__ __launch_bounds__(256) void k_score(const int* __restrict__ batch,
                                               const float* __restrict__ g2,
                                               const float* __restrict__ be2,
                                               const float* __restrict__ Ws2,
                                               const float* __restrict__ bs2,
                                               float invN, int N) {
    __shared__ float es[256];
    __shared__ float sa2[128], sc2[128];
    __shared__ int gid[256];
    int tid = threadIdx.x, lane = tid & 31, warp = tid >> 5;
    int r0 = blockIdx.x * 256;
    int nr = min(256, N - r0);
    gid[tid] = batch[min(r0 + min(tid, nr - 1), N - 1)];
    if (tid < 128) {
        float gg = g2[tid];
        float mu = g_bn2sum[tid] * invN;
        float var = g_bn2sq[tid] * invN - mu * mu;
        float inv = rsqrtf(var + 1e-5f);
        sa2[tid] = gg * inv;
        sc2[tid] = be2[tid] - mu * gg * inv;
    }
    __syncthreads();

    float a2v[4], c2v[4], wv[4];
#pragma unroll
    for (int j = 0; j < 4; j++) {
        int c = 4 * lane + j;
        a2v[j] = sa2[c]; c2v[j] = sc2[c]; wv[j] = Ws2[c];
    }
    float bsv = bs2[0];

    int rbase = warp * 32;
    for (int rr = rbase; rr < rbase + 32; rr += 2) {
        float pA = 0.f, pB = 0.f;
        bool vA = (rr < nr), vB = (rr + 1 < nr);
        if (vA) {
            const bf16* z = g_Z1b + (size_t)(r0 + rr) * D + 4 * lane;
            unsigned u0 = *(const unsigned*)z, u1 = *(const unsigned*)(z + 2);
            float z0, z1, z2, z3; upk(u0, z0, z1); upk(u1, z2, z3);
            pA = fmaxf(a2v[0] * z0 + c2v[0], 0.f) * wv[0]
               + fmaxf(a2v[1] * z1 + c2v[1], 0.f) * wv[1]
               + fmaxf(a2v[2] * z2 + c2v[2], 0.f) * wv[2]
               + fmaxf(a2v[3] * z3 + c2v[3], 0.f) * wv[3];
        }
        if (vB) {
            const bf16* z = g_Z1b + (size_t)(r0 + rr + 1) * D + 4 * lane;
            unsigned u0 = *(const unsigned*)z, u1 = *(const unsigned*)(z + 2);
            float z0, z1, z2, z3; upk(u0, z0, z1); upk(u1, z2, z3);
            pB = fmaxf(a2v[0] * z0 + c2v[0], 0.f) * wv[0]
               + fmaxf(a2v[1] * z1 + c2v[1], 0.f) * wv[1]
               + fmaxf(a2v[2] * z2 + c2v[2], 0.f) * wv[2]
               + fmaxf(a2v[3] * z3 + c2v[3], 0.f) * wv[3];
        }
#pragma unroll
        for (int o = 16; o > 0; o >>= 1) {
            pA += __shfl_xor_sync(0xffffffffu, pA, o);
            pB += __shfl_xor_sync(0xffffffffu, pB, o);
        }
        if (lane == 0) {
            es[rr] = vA ? expf(pA + bsv) : 0.f;
            es[rr + 1] = vB ? expf(pB + bsv) : 0.f;
        }
    }
    __syncthreads();

    int c = tid & 127, half = tid >> 7;
    int rb = half * 128;
    float accn = 0.f, accd = 0.f;
    int cur = gid[rb];
    for (int i = 0; i < 128; i += 4) {
        float v[4], e[4];
#pragma unroll
        for (int j = 0; j < 4; j++) {
            int rr = rb + i + j;
            int r = r0 + rr;
            v[j] = (r < N) ? __bfloat162float(g_hfb[(size_t)r * D + c]) : 0.f;
            e[j] = es[rr];
        }
#pragma unroll
        for (int j = 0; j < 4; j++) {
            int rr = rb + i + j;
            int g = gid[rr];
            if (g != cur) {
                atomicAdd(&g_num[cur * D + c], accn);
                if (c == 0) atomicAdd(&g_den[cur], accd);
                accn = 0.f; accd = 0.f; cur = g;
            }
            if (r0 + rr < N) { accn += e[j] * v[j]; accd += e[j]; }
        }
    }
    atomicAdd(&g_num[cur * D + c], accn);
    if (c == 0) atomicAdd(&g_den[cur], accd);
}

// ---------------- K6: final combine ----------------
__global__ void k_out(float* __restrict__ out, const float* __restrict__ mix) {
    int i = blockIdx.x * blockDim.x + threadIdx.x;
    if (i >= G * D) return;
    int g = i / D;
    float alpha = 1.f / (1.f + expf(-mix[0]));
    float den = g_den[g];
    float wf = (den > 0.f) ? (g_num[i] / den) : 0.f;
    out[i] = alpha * wf + (1.f - alpha) * g_gm[i];
}

// ---------------- launch ----------------
extern "C" void kernel_launch(void* const* d_in, const int* in_sizes, int n_in,
                              void* d_out, int out_size) {
    const float* h   = (const float*)d_in[0];
    const float* sub = (const float*)d_in[1];
    const int* batch = (const int*)d_in[2];
    const float* W1  = (const float*)d_in[3];
    const float* b1  = (const float*)d_in[4];
    const float* g1  = (const float*)d_in[5];
    const float* be1 = (const float*)d_in[6];
    const float* Wg  = (const float*)d_in[7];
    const float* bg  = (const float*)d_in[8];
    const float* Ws1 = (const float*)d_in[9];
    const float* bs1 = (const float*)d_in[10];
    const float* g2  = (const float*)d_in[11];
    const float* be2 = (const float*)d_in[12];
    const float* Ws2 = (const float*)d_in[13];
    const float* bs2 = (const float*)d_in[14];
    const float* mix = (const float*)d_in[15];
    float* out = (float*)d_out;

    int N = in_sizes[0] / D;
    if (N > NMAX) N = NMAX;

    const int SMEM_P1 = 2 * 128 * LDWB * 2 + 512;
    const int SMEM_K3 = (2 * 128 * LDH + 2 * 128 * LDWB) * 2 + 5 * D * 4 + 512;
    cudaFuncSetAttribute(k_pass1, cudaFuncAttributeMaxDynamicSharedMemorySize, SMEM_P1);
    cudaFuncSetAttribute(k_fused, cudaFuncAttributeMaxDynamicSharedMemorySize, SMEM_K3);

    int nb = (N + 127) / 128;
    int nb2 = (N + 255) / 256;
    float invN = 1.f / (float)N;
    k_init<<<(4 * D * S + 255) / 256, 256>>>(W1, Wg, Ws1);
    k_pass1<<<nb, NT, SMEM_P1>>>(h, sub, batch, b1, N);
    k_mid<<<(G * D + 255) / 256, 256>>>(g1, be1, invN);
    k_fused<<<nb, NT, SMEM_K3>>>(batch, b1, bg, bs1, N);
    k_score<<<nb2, 256>>>(batch, g2, be2, Ws2, bs2, invN, N);
    k_out<<<(G * D + 255) / 256, 256>>>(out, mix);
}

// round 11
// speedup vs baseline: 1.0899x; 1.0242x over previous
#include <cuda_runtime.h>
#include <cuda_bf16.h>
#include <math.h>

#define D 128
#define S 64
#define G 256
#define NMAX 400000

#define LDH 136    // bf16 stride, activation tiles: conflict-free
#define LDWB 72    // bf16 stride, [n][k] weight tiles + sub tile: conflict-free
#define NT 256

typedef __nv_bfloat16 bf16;

// ---------------- persistent device scratch (allocation-free) ----------------
__device__ bf16 g_hb[(size_t)NMAX * D];
__device__ bf16 g_subb[(size_t)NMAX * S];
__device__ bf16 g_W1b[D * S];          // [n=128][k=64] transposed
__device__ bf16 g_Wgb[4 * D * S];      // [ck][n][k]
__device__ bf16 g_Ws1b[4 * D * S];     // [ck][n][k]
__device__ bf16 g_hfb[(size_t)NMAX * D];   // h_fused bf16
__device__ bf16 g_Z1b[(size_t)NMAX * D];   // Z1 bf16
__device__ float g_hs[G * D];
__device__ float g_hss[G * D];
__device__ float g_cnt[G];
__device__ float g_bn1sum[D], g_bn1sq[D];
__device__ float g_bn2sum[D], g_bn2sq[D];
__device__ float g_a1[D], g_c1[D];
__device__ float g_gm[G * D], g_gisd[G * D];
__device__ float g_num[G * D];
__device__ float g_den[G];

extern __shared__ float dynsmem[];

// ---------------- helpers ----------------
__device__ __forceinline__ void cp16(void* dst_smem, const void* src) {
    unsigned a = (unsigned)__cvta_generic_to_shared(dst_smem);
    asm volatile("cp.async.cg.shared.global [%0], [%1], 16;\n" :: "r"(a), "l"(src));
}
__device__ __forceinline__ void cp_commit() { asm volatile("cp.async.commit_group;\n"); }
template <int NN> __device__ __forceinline__ void cp_wait() {
    asm volatile("cp.async.wait_group %0;\n" :: "n"(NN));
}

__device__ __forceinline__ unsigned smem_u32(const void* p) {
    return (unsigned)__cvta_generic_to_shared(p);
}

__device__ __forceinline__ unsigned pk(float lo, float hi) {
    unsigned r;
    asm("cvt.rn.bf16x2.f32 %0, %1, %2;" : "=r"(r) : "f"(hi), "f"(lo));
    return r;
}
__device__ __forceinline__ void upk(unsigned v, float& lo, float& hi) {
    lo = __uint_as_float(v << 16);
    hi = __uint_as_float(v & 0xffff0000u);
}

__device__ __forceinline__ void mma_bf16(float* d, const unsigned* a, unsigned b0, unsigned b1) {
    asm volatile(
        "mma.sync.aligned.m16n8k16.row.col.f32.bf16.bf16.f32 "
        "{%0,%1,%2,%3}, {%4,%5,%6,%7}, {%8,%9}, {%0,%1,%2,%3};\n"
        : "+f"(d[0]), "+f"(d[1]), "+f"(d[2]), "+f"(d[3])
        : "r"(a[0]), "r"(a[1]), "r"(a[2]), "r"(a[3]), "r"(b0), "r"(b1));
}

__device__ __forceinline__ void ldsm4(unsigned* r, unsigned addr) {
    asm volatile("ldmatrix.sync.aligned.m8n8.x4.shared.b16 {%0,%1,%2,%3}, [%4];"
        : "=r"(r[0]), "=r"(r[1]), "=r"(r[2]), "=r"(r[3]) : "r"(addr));
}
__device__ __forceinline__ void ldsm2(unsigned& r0, unsigned& r1, unsigned addr) {
    asm volatile("ldmatrix.sync.aligned.m8n8.x2.shared.b16 {%0,%1}, [%2];"
        : "=r"(r0), "=r"(r1) : "r"(addr));
}

// 64-deep K chunk via ldmatrix; warp computes 32(M)x64(N) of a 128x128 tile. 8 warps.
__device__ __forceinline__ void mma_chunk(float (&acc)[2][8][4],
                                          const bf16* sA, int lda, int kcol0,
                                          const bf16* sB, int wm, int wn, int lane) {
    unsigned aBase0 = smem_u32(sA + (wm * 32 + (lane & 15)) * lda + kcol0 + (lane >> 4) * 8);
    unsigned aBase1 = aBase0 + 16 * lda * 2;
    unsigned bBase = smem_u32(sB + (wn * 64 + (lane & 7)) * LDWB + ((lane >> 3) & 1) * 8);
#pragma unroll
    for (int ks = 0; ks < 4; ks++) {
        unsigned a0[4], a1[4];
        ldsm4(a0, aBase0 + ks * 32);
        ldsm4(a1, aBase1 + ks * 32);
#pragma unroll
        for (int nt = 0; nt < 8; nt++) {
            unsigned b0, b1;
            ldsm2(b0, b1, bBase + ks * 32 + nt * (8 * LDWB * 2));
            mma_bf16(acc[0][nt], a0, b0, b1);
            mma_bf16(acc[1][nt], a1, b0, b1);
        }
    }
}

__device__ __forceinline__ void load_wchunk(bf16* buf, const bf16* Wsrc, int tid) {
#pragma unroll
    for (int j = 0; j < 4; j++) {
        int idx = tid + j * NT;
        int n = idx >> 3, f = idx & 7;
        cp16(buf + n * LDWB + f * 8, Wsrc + n * 64 + f * 8);
    }
}

// ---------------- K0: zero accumulators + weight prep (merged) ----------------
__global__ void k_init(const float* __restrict__ W1, const float* __restrict__ Wg,
                       const float* __restrict__ Ws1) {
    int i = blockIdx.x * blockDim.x + threadIdx.x;
    if (i < G * D) { g_hs[i] = 0.f; g_hss[i] = 0.f; g_num[i] = 0.f; }
    if (i < G) { g_cnt[i] = 0.f; g_den[i] = 0.f; }
    if (i < D) { g_bn1sum[i] = 0.f; g_bn1sq[i] = 0.f; g_bn2sum[i] = 0.f; g_bn2sq[i] = 0.f; }
    if (i < D * S) {
        int n = i / S, k = i % S;
        g_W1b[i] = __float2bfloat16(W1[k * D + n]);
    }
    if (i < 4 * D * S) {
        int ck = i / (D * S), rem = i % (D * S);
        int n = rem / S, kl = rem % S;
        g_Wgb[i] = __float2bfloat16(Wg[(ck * S + kl) * D + n]);
        g_Ws1b[i] = __float2bfloat16(Ws1[(ck * S + kl) * D + n]);
    }
}

// ---------------- K1: single-read h (stats + bf16 emit) + sub emit + BN1 stats ----------------
__global__ __launch_bounds__(NT, 2) void k_pass1(const float* __restrict__ h,
                                                 const float* __restrict__ sub,
                                                 const int* __restrict__ batch,
                                                 const float* __restrict__ b1, int N) {
    bf16* Sb = (bf16*)dynsmem;                 // [128][LDWB]
    bf16* Wp = Sb + 128 * LDWB;                // [128][LDWB]
    int* gid = (int*)(Wp + 128 * LDWB);        // [128]
    int tid = threadIdx.x, lane = tid & 31, warp = tid >> 5;
    int wm = warp >> 1, wn = warp & 1;
    int r0 = blockIdx.x * 128;

    load_wchunk(Wp, g_W1b, tid);
    cp_commit();
    if (tid < 128) gid[tid] = batch[min(r0 + tid, N - 1)];

    // sub: fp32 -> bf16 into Sb smem + g_subb global
    for (int i = tid; i < 128 * 32; i += NT) {
        int r = i >> 5, p2 = i & 31;
        int rr = min(r0 + r, N - 1);
        float2 v = *(const float2*)(sub + (size_t)rr * S + p2 * 2);
        unsigned w = pk(v.x, v.y);
        *(unsigned*)(Sb + r * LDWB + p2 * 2) = w;
        if (r0 + r < N) *(unsigned*)(g_subb + (size_t)(r0 + r) * S + p2 * 2) = w;
    }
    __syncthreads();   // gid visible

    // --- h: ONE fp32 read -> bf16 emit + segment stats ---
    {
        int p2 = tid & 63;
        int c = p2 * 2;
        int q = tid >> 6;                      // 0..3
        int rbeg = q * 32;
        float s0 = 0.f, s1 = 0.f, q0 = 0.f, q1 = 0.f, cf = 0.f;
        int cur = gid[rbeg];
        for (int i = 0; i < 32; i += 4) {
            float2 v[4];
#pragma unroll
            for (int j = 0; j < 4; j++) {
                int rg = r0 + rbeg + i + j;
                v[j] = (rg < N) ? *(const float2*)(h + (size_t)rg * D + c)
                                : make_float2(0.f, 0.f);
            }
#pragma unroll
            for (int j = 0; j < 4; j++) {
                int rr = rbeg + i + j;
                int rg = r0 + rr;
                if (rg < N)
                    *(unsigned*)(g_hb + (size_t)rg * D + c) = pk(v[j].x, v[j].y);
                int g = gid[rr];
                if (g != cur) {
                    atomicAdd(&g_hs[cur * D + c], s0);
                    atomicAdd(&g_hs[cur * D + c + 1], s1);
                    atomicAdd(&g_hss[cur * D + c], q0);
                    atomicAdd(&g_hss[cur * D + c + 1], q1);
                    if (p2 == 0) atomicAdd(&g_cnt[cur], cf);
                    s0 = s1 = q0 = q1 = cf = 0.f;
                    cur = g;
                }
                if (rg < N) {
                    s0 += v[j].x; s1 += v[j].y;
                    q0 += v[j].x * v[j].x; q1 += v[j].y * v[j].y;
                    cf += 1.f;
                }
            }
        }
        atomicAdd(&g_hs[cur * D + c], s0);
        atomicAdd(&g_hs[cur * D + c + 1], s1);
        atomicAdd(&g_hss[cur * D + c], q0);
        atomicAdd(&g_hss[cur * D + c + 1], q1);
        if (p2 == 0) atomicAdd(&g_cnt[cur], cf);
    }

    // --- BN1 stats via bf16 mma from accumulators ---
    cp_wait<0>();
    __syncthreads();

    float acc[2][8][4];
#pragma unroll
    for (int mt = 0; mt < 2; mt++)
#pragma unroll
        for (int nt = 0; nt < 8; nt++)
#pragma unroll
            for (int e = 0; e < 4; e++) acc[mt][nt][e] = 0.f;

    mma_chunk(acc, Sb, LDWB, 0, Wp, wm, wn, lane);

    int g4 = lane >> 2, t4 = lane & 3;
#pragma unroll
    for (int nt = 0; nt < 8; nt++)
#pragma unroll
        for (int par = 0; par < 2; par++) {
            int ccol = wn * 64 + nt * 8 + t4 * 2 + par;
            float bb = b1[ccol];
            float s1 = 0.f, s2 = 0.f;
#pragma unroll
            for (int mt = 0; mt < 2; mt++)
#pragma unroll
                for (int rh = 0; rh < 2; rh++) {
                    int r = r0 + wm * 32 + mt * 16 + g4 + rh * 8;
                    float val = acc[mt][nt][rh * 2 + par] + bb;
                    if (r < N) { s1 += val; s2 += val * val; }
                }
#pragma unroll
            for (int o = 4; o < 32; o <<= 1) {
                s1 += __shfl_xor_sync(0xffffffffu, s1, o);
                s2 += __shfl_xor_sync(0xffffffffu, s2, o);
            }
            if (g4 == 0) {
                atomicAdd(&g_bn1sum[ccol], s1);
                atomicAdd(&g_bn1sq[ccol], s2);
            }
        }
}

// ---------------- K2: graph stat finalize + BN1 finalize ----------------
__global__ void k_mid(const float* __restrict__ gam, const float* __restrict__ bet, float invN) {
    int i = blockIdx.x * blockDim.x + threadIdx.x;
    if (i < G * D) {
        int g = i / D;
        float cnt = fmaxf(g_cnt[g], 1.f);
        float m = g_hs[i] / cnt;
        float v = g_hss[i] / cnt - m * m;
        float sd = sqrtf(fmaxf(v, 1e-8f));
        g_gm[i] = m;
        g_gisd[i] = 1.f / (sd + 1e-8f);
    }
    if (blockIdx.x == 0 && threadIdx.x < D) {
        int c = threadIdx.x;
        float mu = g_bn1sum[c] * invN;
        float var = g_bn1sq[c] * invN - mu * mu;
        float inv = rsqrtf(var + 1e-5f);
        g_a1[c] = gam[c] * inv;
        g_c1[c] = bet[c] - mu * gam[c] * inv;
    }
}

// ---------------- K3: big fused pass (bf16 tiles, ldmatrix, coalesced stores) ----------------
__global__ __launch_bounds__(NT, 2) void k_fused(
    const int* __restrict__ batch,
    const float* __restrict__ b1, const float* __restrict__ bg,
    const float* __restrict__ bs1, int N) {
    bf16* Hb = (bf16*)dynsmem;                 // [128][LDH]  h -> h_dev -> Z1
    bf16* Eb = Hb + 128 * LDH;                 // [128][LDH]  sub_e -> h_fused
    bf16* Wq = Eb + 128 * LDH;                 // [128][LDWB] sub, then pong
    bf16* Wp = Wq + 128 * LDWB;                // [128][LDWB] W1, then ping
    float* pa1 = (float*)(Wp + 128 * LDWB);
    float* pc1 = pa1 + D;
    float* pb1 = pc1 + D;
    float* pbg = pb1 + D;
    float* pbs1 = pbg + D;
    int* gid = (int*)(pbs1 + D);               // [128]

    int tid = threadIdx.x, lane = tid & 31, warp = tid >> 5;
    int wm = warp >> 1, wn = warp & 1;
    int g4 = lane >> 2, t4 = lane & 3;
    int r0 = blockIdx.x * 128;

#pragma unroll
    for (int j = 0; j < 4; j++) {
        int idx = tid + j * NT;
        int r = idx >> 3, f = idx & 7;
        int rr = min(r0 + r, N - 1);
        cp16(Wq + r * LDWB + f * 8, g_subb + (size_t)rr * S + f * 8);
    }
    load_wchunk(Wp, g_W1b, tid);
    cp_commit();
#pragma unroll
    for (int j = 0; j < 8; j++) {
        int idx = tid + j * NT;
        int r = idx >> 4, f = idx & 15;
        int rr = min(r0 + r, N - 1);
        cp16(Hb + r * LDH + f * 8, g_hb + (size_t)rr * D + f * 8);
    }
    cp_commit();

    if (tid < 128) {
        pa1[tid] = g_a1[tid]; pc1[tid] = g_c1[tid]; pb1[tid] = b1[tid];
        pbg[tid] = bg[tid]; pbs1[tid] = bs1[tid];
        gid[tid] = batch[min(r0 + tid, N - 1)];
    }

    float acc[2][8][4];
#pragma unroll
    for (int mt = 0; mt < 2; mt++)
#pragma unroll
        for (int nt = 0; nt < 8; nt++)
#pragma unroll
            for (int e = 0; e < 4; e++) acc[mt][nt][e] = 0.f;

    // ---- mma1: X1 = sub @ W1 ----
    cp_wait<1>();
    __syncthreads();
    mma_chunk(acc, Wq, LDWB, 0, Wp, wm, wn, lane);

    // sub_e epilogue -> Eb
#pragma unroll
    for (int mt = 0; mt < 2; mt++)
#pragma unroll
        for (int nt = 0; nt < 8; nt++)
#pragma unroll
            for (int rh = 0; rh < 2; rh++) {
                int r = wm * 32 + mt * 16 + g4 + rh * 8;
                int c = wn * 64 + nt * 8 + 2 * t4;
                float x0 = acc[mt][nt][rh * 2 + 0] + pb1[c];
                float x1 = acc[mt][nt][rh * 2 + 1] + pb1[c + 1];
                float e0 = fmaxf(pa1[c] * x0 + pc1[c], 0.f);
                float e1 = fmaxf(pa1[c + 1] * x1 + pc1[c + 1], 0.f);
                *(unsigned*)(Eb + r * LDH + c) = pk(e0, e1);
                acc[mt][nt][rh * 2 + 0] = 0.f;
                acc[mt][nt][rh * 2 + 1] = 0.f;
            }
    __syncthreads();

    const bf16* Wtab[8] = { g_Wgb, g_Wgb + 8192, g_Wgb + 16384, g_Wgb + 24576,
                            g_Ws1b, g_Ws1b + 8192, g_Ws1b + 16384, g_Ws1b + 24576 };
    load_wchunk(Wp, Wtab[0], tid); cp_commit();
    load_wchunk(Wq, Wtab[1], tid); cp_commit();

#pragma unroll 1
    for (int k = 0; k < 8; k++) {
        if (k < 6) cp_wait<1>(); else cp_wait<0>();
        __syncthreads();
        bf16* buf = (k & 1) ? Wq : Wp;
        const bf16* A = (k < 2) ? Hb : (k < 6) ? Eb : Hb;
        mma_chunk(acc, A, LDH, (k & 1) * 64, buf, wm, wn, lane);
        __syncthreads();
        if (k + 2 < 8) { load_wchunk(buf, Wtab[k + 2], tid); cp_commit(); }

        if (k == 3) {
            // merged gate + h_dev epilogue (smem only; h_fused store deferred)
#pragma unroll
            for (int mt = 0; mt < 2; mt++)
#pragma unroll
                for (int nt = 0; nt < 8; nt++)
#pragma unroll
                    for (int rh = 0; rh < 2; rh++) {
                        int r = wm * 32 + mt * 16 + g4 + rh * 8;
                        int c = wn * 64 + nt * 8 + 2 * t4;
                        float gx0 = acc[mt][nt][rh * 2 + 0] + pbg[c];
                        float gx1 = acc[mt][nt][rh * 2 + 1] + pbg[c + 1];
                        float gt0 = 1.f / (1.f + expf(-gx0));
                        float gt1 = 1.f / (1.f + expf(-gx1));
                        float h0, h1, s0, s1;
                        upk(*(const unsigned*)(Hb + r * LDH + c), h0, h1);
                        upk(*(const unsigned*)(Eb + r * LDH + c), s0, s1);
                        *(unsigned*)(Eb + r * LDH + c) = pk(h0 + gt0 * s0, h1 + gt1 * s1);
                        int g = gid[r];
                        float2 m2 = *(const float2*)(g_gm + g * D + c);
                        float2 i2 = *(const float2*)(g_gisd + g * D + c);
                        *(unsigned*)(Hb + r * LDH + c) =
                            pk((h0 - m2.x) * i2.x, (h1 - m2.y) * i2.y);
                        acc[mt][nt][rh * 2 + 0] = 0.f;
                        acc[mt][nt][rh * 2 + 1] = 0.f;
                    }
            __syncthreads();
        }
    }

    // BN2 stats from fp32 accumulators
#pragma unroll
    for (int nt = 0; nt < 8; nt++)
#pragma unroll
        for (int par = 0; par < 2; par++) {
            int ccol = wn * 64 + nt * 8 + 2 * t4 + par;
            float bb = pbs1[ccol];
            float s1 = 0.f, s2 = 0.f;
#pragma unroll
            for (int mt = 0; mt < 2; mt++)
#pragma unroll
                for (int rh = 0; rh < 2; rh++) {
                    int r = r0 + wm * 32 + mt * 16 + g4 + rh * 8;
                    float val = acc[mt][nt][rh * 2 + par] + bb;
                    if (r < N) { s1 += val; s2 += val * val; }
                }
#pragma unroll
            for (int o = 4; o < 32; o <<= 1) {
                s1 += __shfl_xor_sync(0xffffffffu, s1, o);
                s2 += __shfl_xor_sync(0xffffffffu, s2, o);
            }
            if (g4 == 0) {
                atomicAdd(&g_bn2sum[ccol], s1);
                atomicAdd(&g_bn2sq[ccol], s2);
            }
        }

    // Z1 fragments -> Hb (warp-private rows: no cross-warp hazard)
#pragma unroll
    for (int mt = 0; mt < 2; mt++)
#pragma unroll
        for (int nt = 0; nt < 8; nt++)
#pragma unroll
            for (int rh = 0; rh < 2; rh++) {
                int r = wm * 32 + mt * 16 + g4 + rh * 8;
                int c = wn * 64 + nt * 8 + 2 * t4;
                float z0 = acc[mt][nt][rh * 2 + 0] + pbs1[c];
                float z1 = acc[mt][nt][rh * 2 + 1] + pbs1[c + 1];
                *(unsigned*)(Hb + r * LDH + c) = pk(z0, z1);
            }
    __syncthreads();

    // coalesced 16B stores: Eb -> g_hfb, Hb -> g_Z1b
    for (int idx = tid; idx < 128 * 16; idx += NT) {
        int r = idx >> 4, f = idx & 15;
        if (r0 + r < N) {
            *(uint4*)(g_hfb + (size_t)(r0 + r) * D + f * 8) =
                *(const uint4*)(Eb + r * LDH + f * 8);
            *(uint4*)(g_Z1b + (size_t)(r0 + r) * D + f * 8) =
                *(const uint4*)(Hb + r * LDH + f * 8);
        }
    }
}

// ---------------- K5: BN2 finalize + logits + exp + weighted segment sums ----------------
__global__ __launch_bounds__(256) void k_score(const int* __restrict__ batch,
                                               const float* __restrict__ g2,
                                               const float* __restrict__ be2,
                                               const float* __restrict__ Ws2,
                                               const float* __restrict__ bs2,
                                               float invN, int N) {
    __shared__ float es[256];
    __shared__ float sa2[128], sc2[128];
    __shared__ int gid[256];
    int tid = threadIdx.x, lane = tid & 31, warp = tid >> 5;
    int r0 = blockIdx.x * 256;
    int nr = min(256, N - r0);
    gid[tid] = batch[min(r0 + min(tid, nr - 1), N - 1)];
    if (tid < 128) {
        float gg = g2[tid];
        float mu = g_bn2sum[tid] * invN;
        float var = g_bn2sq[tid] * invN - mu * mu;
        float inv = rsqrtf(var + 1e-5f);
        sa2[tid] = gg * inv;
        sc2[tid] = be2[tid] - mu * gg * inv;
    }
    __syncthreads();

    float a2v[4], c2v[4], wv[4];
#pragma unroll
    for (int j = 0; j < 4; j++) {
        int c = 4 * lane + j;
        a2v[j] = sa2[c]; c2v[j] = sc2[c]; wv[j] = Ws2[c];
    }
    float bsv = bs2[0];

    int rbase = warp * 32;
    for (int rr = rbase; rr < rbase + 32; rr += 2) {
        float pA = 0.f, pB = 0.f;
        bool vA = (rr < nr), vB = (rr + 1 < nr);
        if (vA) {
            const bf16* z = g_Z1b + (size_t)(r0 + rr) * D + 4 * lane;
            unsigned u0 = *(const unsigned*)z, u1 = *(const unsigned*)(z + 2);
            float z0, z1, z2, z3; upk(u0, z0, z1); upk(u1, z2, z3);
            pA = fmaxf(a2v[0] * z0 + c2v[0], 0.f) * wv[0]
               + fmaxf(a2v[1] * z1 + c2v[1], 0.f) * wv[1]
               + fmaxf(a2v[2] * z2 + c2v[2], 0.f) * wv[2]
               + fmaxf(a2v[3] * z3 + c2v[3], 0.f) * wv[3];
        }
        if (vB) {
            const bf16* z = g_Z1b + (size_t)(r0 + rr + 1) * D + 4 * lane;
            unsigned u0 = *(const unsigned*)z, u1 = *(const unsigned*)(z + 2);
            float z0, z1, z2, z3; upk(u0, z0, z1); upk(u1, z2, z3);
            pB = fmaxf(a2v[0] * z0 + c2v[0], 0.f) * wv[0]
               + fmaxf(a2v[1] * z1 + c2v[1], 0.f) * wv[1]
               + fmaxf(a2v[2] * z2 + c2v[2], 0.f) * wv[2]
               + fmaxf(a2v[3] * z3 + c2v[3], 0.f) * wv[3];
        }
#pragma unroll
        for (int o = 16; o > 0; o >>= 1) {
            pA += __shfl_xor_sync(0xffffffffu, pA, o);
            pB += __shfl_xor_sync(0xffffffffu, pB, o);
        }
        if (lane == 0) {
            es[rr] = vA ? expf(pA + bsv) : 0.f;
            es[rr + 1] = vB ? expf(pB + bsv) : 0.f;
        }
    }
    __syncthreads();

    // phase 2: thread owns column-pair c=2*(tid&63), contiguous rows q*64..q*64+63
    {
        int p2 = tid & 63;
        int c = p2 * 2;
        int q = tid >> 6;
        int rb = q * 64;
        float an0 = 0.f, an1 = 0.f, ad = 0.f;
        int cur = gid[rb];
        for (int i = 0; i < 64; i += 4) {
            unsigned u[4]; float e[4];
#pragma unroll
            for (int j = 0; j < 4; j++) {
                int rr = rb + i + j;
                int r = r0 + rr;
                u[j] = (r < N) ? *(const unsigned*)(g_hfb + (size_t)r * D + c) : 0u;
                e[j] = es[rr];
            }
#pragma unroll
            for (int j = 0; j < 4; j++) {
                int rr = rb + i + j;
                int g = gid[rr];
                if (g != cur) {
                    atomicAdd(&g_num[cur * D + c], an0);
                    atomicAdd(&g_num[cur * D + c + 1], an1);
                    if (p2 == 0) atomicAdd(&g_den[cur], ad);
                    an0 = an1 = ad = 0.f;
                    cur = g;
                }
                if (r0 + rr < N) {
                    float v0, v1; upk(u[j], v0, v1);
                    an0 += e[j] * v0; an1 += e[j] * v1; ad += e[j];
                }
            }
        }
        atomicAdd(&g_num[cur * D + c], an0);
        atomicAdd(&g_num[cur * D + c + 1], an1);
        if (p2 == 0) atomicAdd(&g_den[cur], ad);
    }
}

// ---------------- K6: final combine ----------------
__global__ void k_out(float* __restrict__ out, const float* __restrict__ mix) {
    int i = blockIdx.x * blockDim.x + threadIdx.x;
    if (i >= G * D) return;
    int g = i / D;
    float alpha = 1.f / (1.f + expf(-mix[0]));
    float den = g_den[g];
    float wf = (den > 0.f) ? (g_num[i] / den) : 0.f;
    out[i] = alpha * wf + (1.f - alpha) * g_gm[i];
}

// ---------------- launch ----------------
extern "C" void kernel_launch(void* const* d_in, const int* in_sizes, int n_in,
                              void* d_out, int out_size) {
    const float* h   = (const float*)d_in[0];
    const float* sub = (const float*)d_in[1];
    const int* batch = (const int*)d_in[2];
    const float* W1  = (const float*)d_in[3];
    const float* b1  = (const float*)d_in[4];
    const float* g1  = (const float*)d_in[5];
    const float* be1 = (const float*)d_in[6];
    const float* Wg  = (const float*)d_in[7];
    const float* bg  = (const float*)d_in[8];
    const float* Ws1 = (const float*)d_in[9];
    const float* bs1 = (const float*)d_in[10];
    const float* g2  = (const float*)d_in[11];
    const float* be2 = (const float*)d_in[12];
    const float* Ws2 = (const float*)d_in[13];
    const float* bs2 = (const float*)d_in[14];
    const float* mix = (const float*)d_in[15];
    float* out = (float*)d_out;

    int N = in_sizes[0] / D;
    if (N > NMAX) N = NMAX;

    const int SMEM_P1 = 2 * 128 * LDWB * 2 + 512;
    const int SMEM_K3 = (2 * 128 * LDH + 2 * 128 * LDWB) * 2 + 5 * D * 4 + 512;
    cudaFuncSetAttribute(k_pass1, cudaFuncAttributeMaxDynamicSharedMemorySize, SMEM_P1);
    cudaFuncSetAttribute(k_fused, cudaFuncAttributeMaxDynamicSharedMemorySize, SMEM_K3);

    int nb = (N + 127) / 128;
    int nb2 = (N + 255) / 256;
    float invN = 1.f / (float)N;
    k_init<<<(4 * D * S + 255) / 256, 256>>>(W1, Wg, Ws1);
    k_pass1<<<nb, NT, SMEM_P1>>>(h, sub, batch, b1, N);
    k_mid<<<(G * D + 255) / 256, 256>>>(g1, be1, invN);
    k_fused<<<nb, NT, SMEM_K3>>>(batch, b1, bg, bs1, N);
    k_score<<<nb2, 256>>>(batch, g2, be2, Ws2, bs2, invN, N);
    k_out<<<(G * D + 255) / 256, 256>>>(out, mix);
}

// round 15
// speedup vs baseline: 1.1133x; 1.0214x over previous
#include <cuda_runtime.h>
#include <cuda_bf16.h>
#include <math.h>
#include <stdint.h>

#define D 128
#define S 64
#define G 256
#define NMAX 400000

#define LDH 136    // bf16 stride, activation tiles: conflict-free
#define LDWB 72    // bf16 stride, [n][k] weight tiles + sub tile: conflict-free
#define NT 256

typedef __nv_bfloat16 bf16;

// ---------------- persistent device scratch (allocation-free) ----------------
__device__ bf16 g_hb[(size_t)NMAX * D];
__device__ bf16 g_subb[(size_t)NMAX * S];
__device__ bf16 g_W1b[D * S];          // [n=128][k=64] transposed
__device__ bf16 g_Wgb[4 * D * S];      // [ck][n][k]
__device__ bf16 g_Ws1b[4 * D * S];     // [ck][n][k]
__device__ bf16 g_hfb[(size_t)NMAX * D];   // h_fused bf16
__device__ bf16 g_Z1b[(size_t)NMAX * D];   // Z1 bf16
__device__ float g_hs[G * D];
__device__ float g_hss[G * D];
__device__ float g_cnt[G];
__device__ float g_bn1sum[D], g_bn1sq[D];
__device__ float g_bn2sum[D], g_bn2sq[D];
__device__ float g_a1[D], g_c1[D];
__device__ float g_gm[G * D], g_gisd[G * D];
__device__ float g_num[G * D];
__device__ float g_den[G];

extern __shared__ float dynsmem[];

// ---------------- helpers ----------------
__device__ __forceinline__ void cp16(void* dst_smem, const void* src) {
    unsigned a = (unsigned)__cvta_generic_to_shared(dst_smem);
    asm volatile("cp.async.cg.shared.global [%0], [%1], 16;\n" :: "r"(a), "l"(src));
}
__device__ __forceinline__ void cp_commit() { asm volatile("cp.async.commit_group;\n"); }
template <int NN> __device__ __forceinline__ void cp_wait() {
    asm volatile("cp.async.wait_group %0;\n" :: "n"(NN));
}

__device__ __forceinline__ unsigned smem_u32(const void* p) {
    return (unsigned)__cvta_generic_to_shared(p);
}

__device__ __forceinline__ unsigned pk(float lo, float hi) {
    unsigned r;
    asm("cvt.rn.bf16x2.f32 %0, %1, %2;" : "=r"(r) : "f"(hi), "f"(lo));
    return r;
}
__device__ __forceinline__ void upk(unsigned v, float& lo, float& hi) {
    lo = __uint_as_float(v << 16);
    hi = __uint_as_float(v & 0xffff0000u);
}
__device__ __forceinline__ float fsig(float x) {
    return __fdividef(1.f, 1.f + __expf(-x));
}

__device__ __forceinline__ void mma_bf16(float* d, const unsigned* a, unsigned b0, unsigned b1) {
    asm volatile(
        "mma.sync.aligned.m16n8k16.row.col.f32.bf16.bf16.f32 "
        "{%0,%1,%2,%3}, {%4,%5,%6,%7}, {%8,%9}, {%0,%1,%2,%3};\n"
        : "+f"(d[0]), "+f"(d[1]), "+f"(d[2]), "+f"(d[3])
        : "r"(a[0]), "r"(a[1]), "r"(a[2]), "r"(a[3]), "r"(b0), "r"(b1));
}

__device__ __forceinline__ void ldsm4(unsigned* r, unsigned addr) {
    asm volatile("ldmatrix.sync.aligned.m8n8.x4.shared.b16 {%0,%1,%2,%3}, [%4];"
        : "=r"(r[0]), "=r"(r[1]), "=r"(r[2]), "=r"(r[3]) : "r"(addr));
}
__device__ __forceinline__ void ldsm2(unsigned& r0, unsigned& r1, unsigned addr) {
    asm volatile("ldmatrix.sync.aligned.m8n8.x2.shared.b16 {%0,%1}, [%2];"
        : "=r"(r0), "=r"(r1) : "r"(addr));
}

// 64-deep K chunk via ldmatrix; warp computes 32(M)x64(N) of a 128x128 tile. 8 warps.
__device__ __forceinline__ void mma_chunk(float (&acc)[2][8][4],
                                          const bf16* sA, int lda, int kcol0,
                                          const bf16* sB, int wm, int wn, int lane) {
    unsigned aBase0 = smem_u32(sA + (wm * 32 + (lane & 15)) * lda + kcol0 + (lane >> 4) * 8);
    unsigned aBase1 = aBase0 + 16 * lda * 2;
    unsigned bBase = smem_u32(sB + (wn * 64 + (lane & 7)) * LDWB + ((lane >> 3) & 1) * 8);
#pragma unroll
    for (int ks = 0; ks < 4; ks++) {
        unsigned a0[4], a1[4];
        ldsm4(a0, aBase0 + ks * 32);
        ldsm4(a1, aBase1 + ks * 32);
#pragma unroll
        for (int nt = 0; nt < 8; nt++) {
            unsigned b0, b1;
            ldsm2(b0, b1, bBase + ks * 32 + nt * (8 * LDWB * 2));
            mma_bf16(acc[0][nt], a0, b0, b1);
            mma_bf16(acc[1][nt], a1, b0, b1);
        }
    }
}

__device__ __forceinline__ void load_wchunk(bf16* buf, const bf16* Wsrc, int tid) {
#pragma unroll
    for (int j = 0; j < 4; j++) {
        int idx = tid + j * NT;
        int n = idx >> 3, f = idx & 7;
        cp16(buf + n * LDWB + f * 8, Wsrc + n * 64 + f * 8);
    }
}

// ---------------- K0: zero accumulators + weight prep (merged) ----------------
__global__ void k_init(const float* __restrict__ W1, const float* __restrict__ Wg,
                       const float* __restrict__ Ws1) {
    int i = blockIdx.x * blockDim.x + threadIdx.x;
    if (i < G * D) { g_hs[i] = 0.f; g_hss[i] = 0.f; g_num[i] = 0.f; }
    if (i < G) { g_cnt[i] = 0.f; g_den[i] = 0.f; }
    if (i < D) { g_bn1sum[i] = 0.f; g_bn1sq[i] = 0.f; g_bn2sum[i] = 0.f; g_bn2sq[i] = 0.f; }
    if (i < D * S) {
        int n = i / S, k = i % S;
        g_W1b[i] = __float2bfloat16(W1[k * D + n]);
    }
    if (i < 4 * D * S) {
        int ck = i / (D * S), rem = i % (D * S);
        int n = rem / S, kl = rem % S;
        g_Wgb[i] = __float2bfloat16(Wg[(ck * S + kl) * D + n]);
        g_Ws1b[i] = __float2bfloat16(Ws1[(ck * S + kl) * D + n]);
    }
}

// ---------------- K1: single-read h (stats + bf16 emit) + sub emit + BN1 stats ----------------
__global__ __launch_bounds__(NT, 2) void k_pass1(const float* __restrict__ h,
                                                 const float* __restrict__ sub,
                                                 const int* __restrict__ batch,
                                                 const float* __restrict__ b1, int N) {
    bf16* Sb = (bf16*)dynsmem;                 // [128][LDWB]
    bf16* Wp = Sb + 128 * LDWB;                // [128][LDWB]
    int* gid = (int*)(Wp + 128 * LDWB);        // [128]
    int tid = threadIdx.x, lane = tid & 31, warp = tid >> 5;
    int wm = warp >> 1, wn = warp & 1;
    int r0 = blockIdx.x * 128;

    load_wchunk(Wp, g_W1b, tid);
    cp_commit();
    if (tid < 128) gid[tid] = batch[min(r0 + tid, N - 1)];

    // sub: fp32 -> bf16 into Sb smem + g_subb global
    for (int i = tid; i < 128 * 32; i += NT) {
        int r = i >> 5, p2 = i & 31;
        int rr = min(r0 + r, N - 1);
        float2 v = *(const float2*)(sub + (size_t)rr * S + p2 * 2);
        unsigned w = pk(v.x, v.y);
        *(unsigned*)(Sb + r * LDWB + p2 * 2) = w;
        if (r0 + r < N) *(unsigned*)(g_subb + (size_t)(r0 + r) * S + p2 * 2) = w;
    }
    __syncthreads();   // gid visible

    // --- h: ONE fp32 read -> bf16 emit + segment stats ---
    {
        int p2 = tid & 63;
        int c = p2 * 2;
        int q = tid >> 6;                      // 0..3
        int rbeg = q * 32;
        float s0 = 0.f, s1 = 0.f, q0 = 0.f, q1 = 0.f, cf = 0.f;
        int cur = gid[rbeg];
        for (int i = 0; i < 32; i += 4) {
            float2 v[4];
#pragma unroll
            for (int j = 0; j < 4; j++) {
                int rg = r0 + rbeg + i + j;
                v[j] = (rg < N) ? *(const float2*)(h + (size_t)rg * D + c)
                                : make_float2(0.f, 0.f);
            }
#pragma unroll
            for (int j = 0; j < 4; j++) {
                int rr = rbeg + i + j;
                int rg = r0 + rr;
                if (rg < N)
                    *(unsigned*)(g_hb + (size_t)rg * D + c) = pk(v[j].x, v[j].y);
                int g = gid[rr];
                if (g != cur) {
                    atomicAdd(&g_hs[cur * D + c], s0);
                    atomicAdd(&g_hs[cur * D + c + 1], s1);
                    atomicAdd(&g_hss[cur * D + c], q0);
                    atomicAdd(&g_hss[cur * D + c + 1], q1);
                    if (p2 == 0) atomicAdd(&g_cnt[cur], cf);
                    s0 = s1 = q0 = q1 = cf = 0.f;
                    cur = g;
                }
                if (rg < N) {
                    s0 += v[j].x; s1 += v[j].y;
                    q0 += v[j].x * v[j].x; q1 += v[j].y * v[j].y;
                    cf += 1.f;
                }
            }
        }
        atomicAdd(&g_hs[cur * D + c], s0);
        atomicAdd(&g_hs[cur * D + c + 1], s1);
        atomicAdd(&g_hss[cur * D + c], q0);
        atomicAdd(&g_hss[cur * D + c + 1], q1);
        if (p2 == 0) atomicAdd(&g_cnt[cur], cf);
    }

    // --- BN1 stats via bf16 mma from accumulators ---
    cp_wait<0>();
    __syncthreads();

    float acc[2][8][4];
#pragma unroll
    for (int mt = 0; mt < 2; mt++)
#pragma unroll
        for (int nt = 0; nt < 8; nt++)
#pragma unroll
            for (int e = 0; e < 4; e++) acc[mt][nt][e] = 0.f;

    mma_chunk(acc, Sb, LDWB, 0, Wp, wm, wn, lane);

    int g4 = lane >> 2, t4 = lane & 3;
#pragma unroll
    for (int nt = 0; nt < 8; nt++)
#pragma unroll
        for (int par = 0; par < 2; par++) {
            int ccol = wn * 64 + nt * 8 + t4 * 2 + par;
            float bb = b1[ccol];
            float s1 = 0.f, s2 = 0.f;
#pragma unroll
            for (int mt = 0; mt < 2; mt++)
#pragma unroll
                for (int rh = 0; rh < 2; rh++) {
                    int r = r0 + wm * 32 + mt * 16 + g4 + rh * 8;
                    float val = acc[mt][nt][rh * 2 + par] + bb;
                    if (r < N) { s1 += val; s2 += val * val; }
                }
#pragma unroll
            for (int o = 4; o < 32; o <<= 1) {
                s1 += __shfl_xor_sync(0xffffffffu, s1, o);
                s2 += __shfl_xor_sync(0xffffffffu, s2, o);
            }
            if (g4 == 0) {
                atomicAdd(&g_bn1sum[ccol], s1);
                atomicAdd(&g_bn1sq[ccol], s2);
            }
        }
}

// ---------------- K2: graph stat finalize + BN1 finalize ----------------
__global__ void k_mid(const float* __restrict__ gam, const float* __restrict__ bet, float invN) {
    int i = blockIdx.x * blockDim.x + threadIdx.x;
    if (i < G * D) {
        int g = i / D;
        float cnt = fmaxf(g_cnt[g], 1.f);
        float m = g_hs[i] / cnt;
        float v = g_hss[i] / cnt - m * m;
        float sd = sqrtf(fmaxf(v, 1e-8f));
        g_gm[i] = m;
        g_gisd[i] = 1.f / (sd + 1e-8f);
    }
    if (blockIdx.x == 0 && threadIdx.x < D) {
        int c = threadIdx.x;
        float mu = g_bn1sum[c] * invN;
        float var = g_bn1sq[c] * invN - mu * mu;
        float inv = rsqrtf(var + 1e-5f);
        g_a1[c] = gam[c] * inv;
        g_c1[c] = bet[c] - mu * gam[c] * inv;
    }
}

// ---------------- K3: big fused pass (bf16, ldmatrix, 1-sync loop, gm cache) ----------------
__global__ __launch_bounds__(NT, 2) void k_fused(
    const int* __restrict__ batch,
    const float* __restrict__ b1, const float* __restrict__ bg,
    const float* __restrict__ bs1, int N) {
    bf16* Hb = (bf16*)dynsmem;                 // [128][LDH]  h -> h_dev -> Z1
    bf16* Eb = Hb + 128 * LDH;                 // [128][LDH]  sub_e -> h_fused
    bf16* Wq = Eb + 128 * LDH;                 // [128][LDWB] sub, then odd chunks
    bf16* Wp = Wq + 128 * LDWB;                // [128][LDWB] W1, then even chunks
    float* pa1 = (float*)(Wp + 128 * LDWB);
    float* pc1 = pa1 + D;
    float* pb1 = pc1 + D;
    float* pbg = pb1 + D;
    float* pbs1 = pbg + D;
    int* gid = (int*)(pbs1 + D);               // [128]
    float* pgm = (float*)(gid + 128);          // [3*128]
    float* pgi = pgm + 3 * 128;                // [3*128]

    int tid = threadIdx.x, lane = tid & 31, warp = tid >> 5;
    int wm = warp >> 1, wn = warp & 1;
    int g4 = lane >> 2, t4 = lane & 3;
    int r0 = blockIdx.x * 128;

#pragma unroll
    for (int j = 0; j < 4; j++) {
        int idx = tid + j * NT;
        int r = idx >> 3, f = idx & 7;
        int rr = min(r0 + r, N - 1);
        cp16(Wq + r * LDWB + f * 8, g_subb + (size_t)rr * S + f * 8);
    }
    load_wchunk(Wp, g_W1b, tid);
    cp_commit();
#pragma unroll
    for (int j = 0; j < 8; j++) {
        int idx = tid + j * NT;
        int r = idx >> 4, f = idx & 15;
        int rr = min(r0 + r, N - 1);
        cp16(Hb + r * LDH + f * 8, g_hb + (size_t)rr * D + f * 8);
    }
    cp_commit();

    if (tid < 128) {
        pa1[tid] = g_a1[tid]; pc1[tid] = g_c1[tid]; pb1[tid] = b1[tid];
        pbg[tid] = bg[tid]; pbs1[tid] = bs1[tid];
        gid[tid] = batch[min(r0 + tid, N - 1)];
    }

    float acc[2][8][4];
#pragma unroll
    for (int mt = 0; mt < 2; mt++)
#pragma unroll
        for (int nt = 0; nt < 8; nt++)
#pragma unroll
            for (int e = 0; e < 4; e++) acc[mt][nt][e] = 0.f;

    // ---- mma1: X1 = sub @ W1 ----
    cp_wait<1>();
    __syncthreads();
    int g0 = gid[0];

    mma_chunk(acc, Wq, LDWB, 0, Wp, wm, wn, lane);

    // cache gm/gisd for graphs g0..g0+2 (clamped)
    for (int idx = tid; idx < 3 * 128; idx += NT) {
        int gg = min(g0 + (idx >> 7), G - 1);
        int c = idx & 127;
        pgm[idx] = g_gm[gg * D + c];
        pgi[idx] = g_gisd[gg * D + c];
    }

    // sub_e epilogue -> Eb
#pragma unroll
    for (int mt = 0; mt < 2; mt++)
#pragma unroll
        for (int nt = 0; nt < 8; nt++)
#pragma unroll
            for (int rh = 0; rh < 2; rh++) {
                int r = wm * 32 + mt * 16 + g4 + rh * 8;
                int c = wn * 64 + nt * 8 + 2 * t4;
                float x0 = acc[mt][nt][rh * 2 + 0] + pb1[c];
                float x1 = acc[mt][nt][rh * 2 + 1] + pb1[c + 1];
                float e0 = fmaxf(pa1[c] * x0 + pc1[c], 0.f);
                float e1 = fmaxf(pa1[c + 1] * x1 + pc1[c + 1], 0.f);
                *(unsigned*)(Eb + r * LDH + c) = pk(e0, e1);
                acc[mt][nt][rh * 2 + 0] = 0.f;
                acc[mt][nt][rh * 2 + 1] = 0.f;
            }
    __syncthreads();         // Wq/Wp free; Eb + gm cache visible

    const bf16* Wtab[8] = { g_Wgb, g_Wgb + 8192, g_Wgb + 16384, g_Wgb + 24576,
                            g_Ws1b, g_Ws1b + 8192, g_Ws1b + 16384, g_Ws1b + 24576 };
    load_wchunk(Wp, Wtab[0], tid); cp_commit();   // chunk0 -> Wp (even)

#pragma unroll 1
    for (int k = 0; k < 8; k++) {
        cp_wait<0>();
        __syncthreads();     // chunk k visible; mma k-1 done by all warps

        if (k == 4) {
            // gate + h_dev epilogue (own fragment rows)
#pragma unroll
            for (int mt = 0; mt < 2; mt++)
#pragma unroll
                for (int nt = 0; nt < 8; nt++)
#pragma unroll
                    for (int rh = 0; rh < 2; rh++) {
                        int r = wm * 32 + mt * 16 + g4 + rh * 8;
                        int c = wn * 64 + nt * 8 + 2 * t4;
                        float gt0 = fsig(acc[mt][nt][rh * 2 + 0] + pbg[c]);
                        float gt1 = fsig(acc[mt][nt][rh * 2 + 1] + pbg[c + 1]);
                        float h0, h1, s0, s1;
                        upk(*(const unsigned*)(Hb + r * LDH + c), h0, h1);
                        upk(*(const unsigned*)(Eb + r * LDH + c), s0, s1);
                        *(unsigned*)(Eb + r * LDH + c) = pk(h0 + gt0 * s0, h1 + gt1 * s1);
                        int gio = gid[r] - g0;
                        float2 m2, i2;
                        if (gio < 3) {
                            m2 = *(const float2*)(pgm + gio * 128 + c);
                            i2 = *(const float2*)(pgi + gio * 128 + c);
                        } else {
                            int gg = gid[r];
                            m2 = *(const float2*)(g_gm + gg * D + c);
                            i2 = *(const float2*)(g_gisd + gg * D + c);
                        }
                        *(unsigned*)(Hb + r * LDH + c) =
                            pk((h0 - m2.x) * i2.x, (h1 - m2.y) * i2.y);
                        acc[mt][nt][rh * 2 + 0] = 0.f;
                        acc[mt][nt][rh * 2 + 1] = 0.f;
                    }
            __syncthreads();
            // coalesced h_fused store
            for (int idx = tid; idx < 128 * 16; idx += NT) {
                int r2 = idx >> 4, f = idx & 15;
                if (r0 + r2 < N)
                    *(uint4*)(g_hfb + (size_t)(r0 + r2) * D + f * 8) =
                        *(const uint4*)(Eb + r2 * LDH + f * 8);
            }
        }

        if (k + 1 < 8) {
            // chunk k+1 -> buffer freed by mma k-1
            load_wchunk(((k + 1) & 1) ? Wq : Wp, Wtab[k + 1], tid);
            cp_commit();
        }
        bf16* buf = (k & 1) ? Wq : Wp;
        const bf16* A = (k < 2) ? Hb : (k < 6) ? Eb : Hb;
        mma_chunk(acc, A, LDH, (k & 1) * 64, buf, wm, wn, lane);
    }

    // BN2 stats from fp32 accumulators
#pragma unroll
    for (int nt = 0; nt < 8; nt++)
#pragma unroll
        for (int par = 0; par < 2; par++) {
            int ccol = wn * 64 + nt * 8 + 2 * t4 + par;
            float bb = pbs1[ccol];
            float s1 = 0.f, s2 = 0.f;
#pragma unroll
            for (int mt = 0; mt < 2; mt++)
#pragma unroll
                for (int rh = 0; rh < 2; rh++) {
                    int r = r0 + wm * 32 + mt * 16 + g4 + rh * 8;
                    float val = acc[mt][nt][rh * 2 + par] + bb;
                    if (r < N) { s1 += val; s2 += val * val; }
                }
#pragma unroll
            for (int o = 4; o < 32; o <<= 1) {
                s1 += __shfl_xor_sync(0xffffffffu, s1, o);
                s2 += __shfl_xor_sync(0xffffffffu, s2, o);
            }
            if (g4 == 0) {
                atomicAdd(&g_bn2sum[ccol], s1);
                atomicAdd(&g_bn2sq[ccol], s2);
            }
        }

    // Z1 fragments -> Hb (warp-private rows)
#pragma unroll
    for (int mt = 0; mt < 2; mt++)
#pragma unroll
        for (int nt = 0; nt < 8; nt++)
#pragma unroll
            for (int rh = 0; rh < 2; rh++) {
                int r = wm * 32 + mt * 16 + g4 + rh * 8;
                int c = wn * 64 + nt * 8 + 2 * t4;
                float z0 = acc[mt][nt][rh * 2 + 0] + pbs1[c];
                float z1 = acc[mt][nt][rh * 2 + 1] + pbs1[c + 1];
                *(unsigned*)(Hb + r * LDH + c) = pk(z0, z1);
            }
    __syncthreads();

    // coalesced Z1 store
    for (int idx = tid; idx < 128 * 16; idx += NT) {
        int r2 = idx >> 4, f = idx & 15;
        if (r0 + r2 < N)
            *(uint4*)(g_Z1b + (size_t)(r0 + r2) * D + f * 8) =
                *(const uint4*)(Hb + r2 * LDH + f * 8);
    }
}

// ---------------- K5: BN2 finalize + logits + exp + weighted segment sums ----------------
__global__ __launch_bounds__(256) void k_score(const int* __restrict__ batch,
                                               const float* __restrict__ g2,
                                               const float* __restrict__ be2,
                                               const float* __restrict__ Ws2,
                                               const float* __restrict__ bs2,
                                               float invN, int N) {
    __shared__ float es[256];
    __shared__ float sa2[128], sc2[128];
    __shared__ int gid[256];
    int tid = threadIdx.x, lane = tid & 31, warp = tid >> 5;
    int r0 = blockIdx.x * 256;
    int nr = min(256, N - r0);
    gid[tid] = batch[min(r0 + min(tid, nr - 1), N - 1)];
    if (tid < 128) {
        float gg = g2[tid];
        float mu = g_bn2sum[tid] * invN;
        float var = g_bn2sq[tid] * invN - mu * mu;
        float inv = rsqrtf(var + 1e-5f);
        sa2[tid] = gg * inv;
        sc2[tid] = be2[tid] - mu * gg * inv;
    }
    __syncthreads();

    float a2v[4], c2v[4], wv[4];
#pragma unroll
    for (int j = 0; j < 4; j++) {
        int c = 4 * lane + j;
        a2v[j] = sa2[c]; c2v[j] = sc2[c]; wv[j] = Ws2[c];
    }
    float bsv = bs2[0];

    int rbase = warp * 32;
    for (int rr = rbase; rr < rbase + 32; rr += 2) {
        float pA = 0.f, pB = 0.f;
        bool vA = (rr < nr), vB = (rr + 1 < nr);
        if (vA) {
            const bf16* z = g_Z1b + (size_t)(r0 + rr) * D + 4 * lane;
            unsigned u0 = *(const unsigned*)z, u1 = *(const unsigned*)(z + 2);
            float z0, z1, z2, z3; upk(u0, z0, z1); upk(u1, z2, z3);
            pA = fmaxf(a2v[0] * z0 + c2v[0], 0.f) * wv[0]
               + fmaxf(a2v[1] * z1 + c2v[1], 0.f) * wv[1]
               + fmaxf(a2v[2] * z2 + c2v[2], 0.f) * wv[2]
               + fmaxf(a2v[3] * z3 + c2v[3], 0.f) * wv[3];
        }
        if (vB) {
            const bf16* z = g_Z1b + (size_t)(r0 + rr + 1) * D + 4 * lane;
            unsigned u0 = *(const unsigned*)z, u1 = *(const unsigned*)(z + 2);
            float z0, z1, z2, z3; upk(u0, z0, z1); upk(u1, z2, z3);
            pB = fmaxf(a2v[0] * z0 + c2v[0], 0.f) * wv[0]
               + fmaxf(a2v[1] * z1 + c2v[1], 0.f) * wv[1]
               + fmaxf(a2v[2] * z2 + c2v[2], 0.f) * wv[2]
               + fmaxf(a2v[3] * z3 + c2v[3], 0.f) * wv[3];
        }
#pragma unroll
        for (int o = 16; o > 0; o >>= 1) {
            pA += __shfl_xor_sync(0xffffffffu, pA, o);
            pB += __shfl_xor_sync(0xffffffffu, pB, o);
        }
        if (lane == 0) {
            es[rr] = vA ? __expf(pA + bsv) : 0.f;
            es[rr + 1] = vB ? __expf(pB + bsv) : 0.f;
        }
    }
    __syncthreads();

    // phase 2: thread owns column-pair c=2*(tid&63), contiguous rows q*64..q*64+63
    {
        int p2 = tid & 63;
        int c = 2 * p2;
        int q = tid >> 6;
        int rb = q * 64;
        float an0 = 0.f, an1 = 0.f, ad = 0.f;
        int cur = gid[rb];
        for (int i = 0; i < 64; i += 4) {
            unsigned u[4]; float e[4];
#pragma unroll
            for (int j = 0; j < 4; j++) {
                int rr = rb + i + j;
                int r = r0 + rr;
                u[j] = (r < N) ? *(const unsigned*)(g_hfb + (size_t)r * D + c) : 0u;
                e[j] = es[rr];
            }
#pragma unroll
            for (int j = 0; j < 4; j++) {
                int rr = rb + i + j;
                int g = gid[rr];
                if (g != cur) {
                    atomicAdd(&g_num[cur * D + c], an0);
                    atomicAdd(&g_num[cur * D + c + 1], an1);
                    if (p2 == 0) atomicAdd(&g_den[cur], ad);
                    an0 = an1 = ad = 0.f;
                    cur = g;
                }
                if (r0 + rr < N) {
                    float v0, v1; upk(u[j], v0, v1);
                    an0 += e[j] * v0; an1 += e[j] * v1; ad += e[j];
                }
            }
        }
        atomicAdd(&g_num[cur * D + c], an0);
        atomicAdd(&g_num[cur * D + c + 1], an1);
        if (p2 == 0) atomicAdd(&g_den[cur], ad);
    }
}

// ---------------- K6: final combine ----------------
__global__ void k_out(float* __restrict__ out, const float* __restrict__ mix) {
    int i = blockIdx.x * blockDim.x + threadIdx.x;
    if (i >= G * D) return;
    int g = i / D;
    float alpha = 1.f / (1.f + expf(-mix[0]));
    float den = g_den[g];
    float wf = (den > 0.f) ? (g_num[i] / den) : 0.f;
    out[i] = alpha * wf + (1.f - alpha) * g_gm[i];
}

// ---------------- launch ----------------
extern "C" void kernel_launch(void* const* d_in, const int* in_sizes, int n_in,
                              void* d_out, int out_size) {
    const float* h   = (const float*)d_in[0];
    const float* sub = (const float*)d_in[1];
    const int* batch = (const int*)d_in[2];
    const float* W1  = (const float*)d_in[3];
    const float* b1  = (const float*)d_in[4];
    const float* g1  = (const float*)d_in[5];
    const float* be1 = (const float*)d_in[6];
    const float* Wg  = (const float*)d_in[7];
    const float* bg  = (const float*)d_in[8];
    const float* Ws1 = (const float*)d_in[9];
    const float* bs1 = (const float*)d_in[10];
    const float* g2  = (const float*)d_in[11];
    const float* be2 = (const float*)d_in[12];
    const float* Ws2 = (const float*)d_in[13];
    const float* bs2 = (const float*)d_in[14];
    const float* mix = (const float*)d_in[15];
    float* out = (float*)d_out;

    int N = in_sizes[0] / D;
    if (N > NMAX) N = NMAX;

    const int SMEM_P1 = 2 * 128 * LDWB * 2 + 512;
    const int SMEM_K3 = (2 * 128 * LDH + 2 * 128 * LDWB) * 2 + 5 * D * 4 + 512
                      + 2 * 3 * 128 * 4;
    cudaFuncSetAttribute(k_pass1, cudaFuncAttributeMaxDynamicSharedMemorySize, SMEM_P1);
    cudaFuncSetAttribute(k_fused, cudaFuncAttributeMaxDynamicSharedMemorySize, SMEM_K3);

    int nb = (N + 127) / 128;
    int nb2 = (N + 255) / 256;
    float invN = 1.f / (float)N;
    k_init<<<(4 * D * S + 255) / 256, 256>>>(W1, Wg, Ws1);
    k_pass1<<<nb, NT, SMEM_P1>>>(h, sub, batch, b1, N);
    k_mid<<<(G * D + 255) / 256, 256>>>(g1, be1, invN);
    k_fused<<<nb, NT, SMEM_K3>>>(batch, b1, bg, bs1, N);
    k_score<<<nb2, 256>>>(batch, g2, be2, Ws2, bs2, invN, N);
    k_out<<<(G * D + 255) / 256, 256>>>(out, mix);
}

// round 16
// speedup vs baseline: 1.1484x; 1.0315x over previous
#include <cuda_runtime.h>
#include <cuda_bf16.h>
#include <math.h>
#include <stdint.h>

#define D 128
#define S 64
#define G 256
#define NMAX 400000

#define LDH 136    // bf16 stride, activation tiles: conflict-free
#define LDWB 72    // bf16 stride, [n][k] weight tiles + sub tile: conflict-free
#define NT1 256    // k_pass1 threads
#define NT3 512    // k_fused threads (16 warps)

typedef __nv_bfloat16 bf16;

// ---------------- persistent device scratch (allocation-free) ----------------
__device__ bf16 g_hb[(size_t)NMAX * D];
__device__ bf16 g_subb[(size_t)NMAX * S];
__device__ bf16 g_W1b[D * S];          // [n=128][k=64] transposed
__device__ bf16 g_Wgb[4 * D * S];      // [ck][n][k]
__device__ bf16 g_Ws1b[4 * D * S];     // [ck][n][k]
__device__ bf16 g_hfb[(size_t)NMAX * D];   // h_fused bf16
__device__ bf16 g_Z1b[(size_t)NMAX * D];   // Z1 bf16
__device__ float g_hs[G * D];
__device__ float g_hss[G * D];
__device__ float g_cnt[G];
__device__ float g_bn1sum[D], g_bn1sq[D];
__device__ float g_bn2sum[D], g_bn2sq[D];
__device__ float g_a1[D], g_c1[D];
__device__ float g_gm[G * D], g_gisd[G * D];
__device__ float g_num[G * D];
__device__ float g_den[G];

extern __shared__ float dynsmem[];

// ---------------- helpers ----------------
__device__ __forceinline__ void cp16(void* dst_smem, const void* src) {
    unsigned a = (unsigned)__cvta_generic_to_shared(dst_smem);
    asm volatile("cp.async.cg.shared.global [%0], [%1], 16;\n" :: "r"(a), "l"(src));
}
__device__ __forceinline__ void cp_commit() { asm volatile("cp.async.commit_group;\n"); }
template <int NN> __device__ __forceinline__ void cp_wait() {
    asm volatile("cp.async.wait_group %0;\n" :: "n"(NN));
}

__device__ __forceinline__ unsigned smem_u32(const void* p) {
    return (unsigned)__cvta_generic_to_shared(p);
}

__device__ __forceinline__ unsigned pk(float lo, float hi) {
    unsigned r;
    asm("cvt.rn.bf16x2.f32 %0, %1, %2;" : "=r"(r) : "f"(hi), "f"(lo));
    return r;
}
__device__ __forceinline__ void upk(unsigned v, float& lo, float& hi) {
    lo = __uint_as_float(v << 16);
    hi = __uint_as_float(v & 0xffff0000u);
}
__device__ __forceinline__ float fsig(float x) {
    return __fdividef(1.f, 1.f + __expf(-x));
}

__device__ __forceinline__ void mma_bf16(float* d, const unsigned* a, unsigned b0, unsigned b1) {
    asm volatile(
        "mma.sync.aligned.m16n8k16.row.col.f32.bf16.bf16.f32 "
        "{%0,%1,%2,%3}, {%4,%5,%6,%7}, {%8,%9}, {%0,%1,%2,%3};\n"
        : "+f"(d[0]), "+f"(d[1]), "+f"(d[2]), "+f"(d[3])
        : "r"(a[0]), "r"(a[1]), "r"(a[2]), "r"(a[3]), "r"(b0), "r"(b1));
}

__device__ __forceinline__ void ldsm4(unsigned* r, unsigned addr) {
    asm volatile("ldmatrix.sync.aligned.m8n8.x4.shared.b16 {%0,%1,%2,%3}, [%4];"
        : "=r"(r[0]), "=r"(r[1]), "=r"(r[2]), "=r"(r[3]) : "r"(addr));
}
__device__ __forceinline__ void ldsm2(unsigned& r0, unsigned& r1, unsigned addr) {
    asm volatile("ldmatrix.sync.aligned.m8n8.x2.shared.b16 {%0,%1}, [%2];"
        : "=r"(r0), "=r"(r1) : "r"(addr));
}

// 8-warp variant (k_pass1): warp computes 32(M)x64(N)
__device__ __forceinline__ void mma_chunk8(float (&acc)[2][8][4],
                                           const bf16* sA, int lda, int kcol0,
                                           const bf16* sB, int wm, int wn, int lane) {
    unsigned aBase0 = smem_u32(sA + (wm * 32 + (lane & 15)) * lda + kcol0 + (lane >> 4) * 8);
    unsigned aBase1 = aBase0 + 16 * lda * 2;
    unsigned bBase = smem_u32(sB + (wn * 64 + (lane & 7)) * LDWB + ((lane >> 3) & 1) * 8);
#pragma unroll
    for (int ks = 0; ks < 4; ks++) {
        unsigned a0[4], a1[4];
        ldsm4(a0, aBase0 + ks * 32);
        ldsm4(a1, aBase1 + ks * 32);
#pragma unroll
        for (int nt = 0; nt < 8; nt++) {
            unsigned b0, b1;
            ldsm2(b0, b1, bBase + ks * 32 + nt * (8 * LDWB * 2));
            mma_bf16(acc[0][nt], a0, b0, b1);
            mma_bf16(acc[1][nt], a1, b0, b1);
        }
    }
}

// 16-warp variant (k_fused): warp computes 32(M)x32(N)
__device__ __forceinline__ void mma_chunk16(float (&acc)[2][4][4],
                                            const bf16* sA, int lda, int kcol0,
                                            const bf16* sB, int wm, int wn, int lane) {
    unsigned aBase0 = smem_u32(sA + (wm * 32 + (lane & 15)) * lda + kcol0 + (lane >> 4) * 8);
    unsigned aBase1 = aBase0 + 16 * lda * 2;
    unsigned bBase = smem_u32(sB + (wn * 32 + (lane & 7)) * LDWB + ((lane >> 3) & 1) * 8);
#pragma unroll
    for (int ks = 0; ks < 4; ks++) {
        unsigned a0[4], a1[4];
        ldsm4(a0, aBase0 + ks * 32);
        ldsm4(a1, aBase1 + ks * 32);
#pragma unroll
        for (int nt = 0; nt < 4; nt++) {
            unsigned b0, b1;
            ldsm2(b0, b1, bBase + ks * 32 + nt * (8 * LDWB * 2));
            mma_bf16(acc[0][nt], a0, b0, b1);
            mma_bf16(acc[1][nt], a1, b0, b1);
        }
    }
}

template <int NTH>
__device__ __forceinline__ void load_wchunk(bf16* buf, const bf16* Wsrc, int tid) {
#pragma unroll
    for (int j = 0; j < 1024 / NTH; j++) {
        int idx = tid + j * NTH;
        int n = idx >> 3, f = idx & 7;
        cp16(buf + n * LDWB + f * 8, Wsrc + n * 64 + f * 8);
    }
}

// ---------------- K0: zero accumulators + weight prep (merged) ----------------
__global__ void k_init(const float* __restrict__ W1, const float* __restrict__ Wg,
                       const float* __restrict__ Ws1) {
    int i = blockIdx.x * blockDim.x + threadIdx.x;
    if (i < G * D) { g_hs[i] = 0.f; g_hss[i] = 0.f; g_num[i] = 0.f; }
    if (i < G) { g_cnt[i] = 0.f; g_den[i] = 0.f; }
    if (i < D) { g_bn1sum[i] = 0.f; g_bn1sq[i] = 0.f; g_bn2sum[i] = 0.f; g_bn2sq[i] = 0.f; }
    if (i < D * S) {
        int n = i / S, k = i % S;
        g_W1b[i] = __float2bfloat16(W1[k * D + n]);
    }
    if (i < 4 * D * S) {
        int ck = i / (D * S), rem = i % (D * S);
        int n = rem / S, kl = rem % S;
        g_Wgb[i] = __float2bfloat16(Wg[(ck * S + kl) * D + n]);
        g_Ws1b[i] = __float2bfloat16(Ws1[(ck * S + kl) * D + n]);
    }
}

// ---------------- K1: single-read h (stats + bf16 emit) + sub emit + BN1 stats ----------------
__global__ __launch_bounds__(NT1, 2) void k_pass1(const float* __restrict__ h,
                                                  const float* __restrict__ sub,
                                                  const int* __restrict__ batch,
                                                  const float* __restrict__ b1, int N) {
    bf16* Sb = (bf16*)dynsmem;                 // [128][LDWB]
    bf16* Wp = Sb + 128 * LDWB;                // [128][LDWB]
    int* gid = (int*)(Wp + 128 * LDWB);        // [128]
    int tid = threadIdx.x, lane = tid & 31, warp = tid >> 5;
    int wm = warp >> 1, wn = warp & 1;
    int r0 = blockIdx.x * 128;

    load_wchunk<NT1>(Wp, g_W1b, tid);
    cp_commit();
    if (tid < 128) gid[tid] = batch[min(r0 + tid, N - 1)];

    for (int i = tid; i < 128 * 32; i += NT1) {
        int r = i >> 5, p2 = i & 31;
        int rr = min(r0 + r, N - 1);
        float2 v = *(const float2*)(sub + (size_t)rr * S + p2 * 2);
        unsigned w = pk(v.x, v.y);
        *(unsigned*)(Sb + r * LDWB + p2 * 2) = w;
        if (r0 + r < N) *(unsigned*)(g_subb + (size_t)(r0 + r) * S + p2 * 2) = w;
    }
    __syncthreads();   // gid visible

    {
        int p2 = tid & 63;
        int c = p2 * 2;
        int q = tid >> 6;
        int rbeg = q * 32;
        float s0 = 0.f, s1 = 0.f, q0 = 0.f, q1 = 0.f, cf = 0.f;
        int cur = gid[rbeg];
        for (int i = 0; i < 32; i += 4) {
            float2 v[4];
#pragma unroll
            for (int j = 0; j < 4; j++) {
                int rg = r0 + rbeg + i + j;
                v[j] = (rg < N) ? *(const float2*)(h + (size_t)rg * D + c)
                                : make_float2(0.f, 0.f);
            }
#pragma unroll
            for (int j = 0; j < 4; j++) {
                int rr = rbeg + i + j;
                int rg = r0 + rr;
                if (rg < N)
                    *(unsigned*)(g_hb + (size_t)rg * D + c) = pk(v[j].x, v[j].y);
                int g = gid[rr];
                if (g != cur) {
                    atomicAdd(&g_hs[cur * D + c], s0);
                    atomicAdd(&g_hs[cur * D + c + 1], s1);
                    atomicAdd(&g_hss[cur * D + c], q0);
                    atomicAdd(&g_hss[cur * D + c + 1], q1);
                    if (p2 == 0) atomicAdd(&g_cnt[cur], cf);
                    s0 = s1 = q0 = q1 = cf = 0.f;
                    cur = g;
                }
                if (rg < N) {
                    s0 += v[j].x; s1 += v[j].y;
                    q0 += v[j].x * v[j].x; q1 += v[j].y * v[j].y;
                    cf += 1.f;
                }
            }
        }
        atomicAdd(&g_hs[cur * D + c], s0);
        atomicAdd(&g_hs[cur * D + c + 1], s1);
        atomicAdd(&g_hss[cur * D + c], q0);
        atomicAdd(&g_hss[cur * D + c + 1], q1);
        if (p2 == 0) atomicAdd(&g_cnt[cur], cf);
    }

    cp_wait<0>();
    __syncthreads();

    float acc[2][8][4];
#pragma unroll
    for (int mt = 0; mt < 2; mt++)
#pragma unroll
        for (int nt = 0; nt < 8; nt++)
#pragma unroll
            for (int e = 0; e < 4; e++) acc[mt][nt][e] = 0.f;

    mma_chunk8(acc, Sb, LDWB, 0, Wp, wm, wn, lane);

    int g4 = lane >> 2, t4 = lane & 3;
#pragma unroll
    for (int nt = 0; nt < 8; nt++)
#pragma unroll
        for (int par = 0; par < 2; par++) {
            int ccol = wn * 64 + nt * 8 + t4 * 2 + par;
            float bb = b1[ccol];
            float s1 = 0.f, s2 = 0.f;
#pragma unroll
            for (int mt = 0; mt < 2; mt++)
#pragma unroll
                for (int rh = 0; rh < 2; rh++) {
                    int r = r0 + wm * 32 + mt * 16 + g4 + rh * 8;
                    float val = acc[mt][nt][rh * 2 + par] + bb;
                    if (r < N) { s1 += val; s2 += val * val; }
                }
#pragma unroll
            for (int o = 4; o < 32; o <<= 1) {
                s1 += __shfl_xor_sync(0xffffffffu, s1, o);
                s2 += __shfl_xor_sync(0xffffffffu, s2, o);
            }
            if (g4 == 0) {
                atomicAdd(&g_bn1sum[ccol], s1);
                atomicAdd(&g_bn1sq[ccol], s2);
            }
        }
}

// ---------------- K2: graph stat finalize + BN1 finalize ----------------
__global__ void k_mid(const float* __restrict__ gam, const float* __restrict__ bet, float invN) {
    int i = blockIdx.x * blockDim.x + threadIdx.x;
    if (i < G * D) {
        int g = i / D;
        float cnt = fmaxf(g_cnt[g], 1.f);
        float m = g_hs[i] / cnt;
        float v = g_hss[i] / cnt - m * m;
        float sd = sqrtf(fmaxf(v, 1e-8f));
        g_gm[i] = m;
        g_gisd[i] = 1.f / (sd + 1e-8f);
    }
    if (blockIdx.x == 0 && threadIdx.x < D) {
        int c = threadIdx.x;
        float mu = g_bn1sum[c] * invN;
        float var = g_bn1sq[c] * invN - mu * mu;
        float inv = rsqrtf(var + 1e-5f);
        g_a1[c] = gam[c] * inv;
        g_c1[c] = bet[c] - mu * gam[c] * inv;
    }
}

// ---------------- K3: big fused pass (bf16, ldmatrix, 512 threads, 32x32 warp tile) ----------------
__global__ __launch_bounds__(NT3, 2) void k_fused(
    const int* __restrict__ batch,
    const float* __restrict__ b1, const float* __restrict__ bg,
    const float* __restrict__ bs1, int N) {
    bf16* Hb = (bf16*)dynsmem;                 // [128][LDH]  h -> h_dev -> Z1
    bf16* Eb = Hb + 128 * LDH;                 // [128][LDH]  sub_e -> h_fused
    bf16* Wq = Eb + 128 * LDH;                 // [128][LDWB] sub, then odd chunks
    bf16* Wp = Wq + 128 * LDWB;                // [128][LDWB] W1, then even chunks
    float* pa1 = (float*)(Wp + 128 * LDWB);
    float* pc1 = pa1 + D;
    float* pb1 = pc1 + D;
    float* pbg = pb1 + D;
    float* pbs1 = pbg + D;
    int* gid = (int*)(pbs1 + D);               // [128]
    float* pgm = (float*)(gid + 128);          // [3*128]
    float* pgi = pgm + 3 * 128;                // [3*128]

    int tid = threadIdx.x, lane = tid & 31, warp = tid >> 5;
    int wm = warp >> 2, wn = warp & 3;
    int g4 = lane >> 2, t4 = lane & 3;
    int r0 = blockIdx.x * 128;

#pragma unroll
    for (int j = 0; j < 2; j++) {
        int idx = tid + j * NT3;
        int r = idx >> 3, f = idx & 7;
        int rr = min(r0 + r, N - 1);
        cp16(Wq + r * LDWB + f * 8, g_subb + (size_t)rr * S + f * 8);
    }
    load_wchunk<NT3>(Wp, g_W1b, tid);
    cp_commit();
#pragma unroll
    for (int j = 0; j < 4; j++) {
        int idx = tid + j * NT3;
        int r = idx >> 4, f = idx & 15;
        int rr = min(r0 + r, N - 1);
        cp16(Hb + r * LDH + f * 8, g_hb + (size_t)rr * D + f * 8);
    }
    cp_commit();

    if (tid < 128) {
        pa1[tid] = g_a1[tid]; pc1[tid] = g_c1[tid]; pb1[tid] = b1[tid];
        pbg[tid] = bg[tid]; pbs1[tid] = bs1[tid];
        gid[tid] = batch[min(r0 + tid, N - 1)];
    }

    float acc[2][4][4];
#pragma unroll
    for (int mt = 0; mt < 2; mt++)
#pragma unroll
        for (int nt = 0; nt < 4; nt++)
#pragma unroll
            for (int e = 0; e < 4; e++) acc[mt][nt][e] = 0.f;

    // ---- mma1: X1 = sub @ W1 ----
    cp_wait<1>();
    __syncthreads();
    int g0 = gid[0];

    mma_chunk16(acc, Wq, LDWB, 0, Wp, wm, wn, lane);

    // cache gm/gisd for graphs g0..g0+2 (clamped)
    for (int idx = tid; idx < 3 * 128; idx += NT3) {
        int gg = min(g0 + (idx >> 7), G - 1);
        int c = idx & 127;
        pgm[idx] = g_gm[gg * D + c];
        pgi[idx] = g_gisd[gg * D + c];
    }

    // sub_e epilogue -> Eb
#pragma unroll
    for (int mt = 0; mt < 2; mt++)
#pragma unroll
        for (int nt = 0; nt < 4; nt++)
#pragma unroll
            for (int rh = 0; rh < 2; rh++) {
                int r = wm * 32 + mt * 16 + g4 + rh * 8;
                int c = wn * 32 + nt * 8 + 2 * t4;
                float x0 = acc[mt][nt][rh * 2 + 0] + pb1[c];
                float x1 = acc[mt][nt][rh * 2 + 1] + pb1[c + 1];
                float e0 = fmaxf(pa1[c] * x0 + pc1[c], 0.f);
                float e1 = fmaxf(pa1[c + 1] * x1 + pc1[c + 1], 0.f);
                *(unsigned*)(Eb + r * LDH + c) = pk(e0, e1);
                acc[mt][nt][rh * 2 + 0] = 0.f;
                acc[mt][nt][rh * 2 + 1] = 0.f;
            }
    __syncthreads();         // Wq/Wp free; Eb + gm cache visible

    const bf16* Wtab[8] = { g_Wgb, g_Wgb + 8192, g_Wgb + 16384, g_Wgb + 24576,
                            g_Ws1b, g_Ws1b + 8192, g_Ws1b + 16384, g_Ws1b + 24576 };
    load_wchunk<NT3>(Wp, Wtab[0], tid); cp_commit();   // chunk0 -> Wp (even)

#pragma unroll 1
    for (int k = 0; k < 8; k++) {
        cp_wait<0>();
        __syncthreads();     // chunk k visible; mma k-1 done by all warps

        if (k == 4) {
            // gate + h_dev epilogue (own fragment rows)
#pragma unroll
            for (int mt = 0; mt < 2; mt++)
#pragma unroll
                for (int nt = 0; nt < 4; nt++)
#pragma unroll
                    for (int rh = 0; rh < 2; rh++) {
                        int r = wm * 32 + mt * 16 + g4 + rh * 8;
                        int c = wn * 32 + nt * 8 + 2 * t4;
                        float gt0 = fsig(acc[mt][nt][rh * 2 + 0] + pbg[c]);
                        float gt1 = fsig(acc[mt][nt][rh * 2 + 1] + pbg[c + 1]);
                        float h0, h1, s0, s1;
                        upk(*(const unsigned*)(Hb + r * LDH + c), h0, h1);
                        upk(*(const unsigned*)(Eb + r * LDH + c), s0, s1);
                        *(unsigned*)(Eb + r * LDH + c) = pk(h0 + gt0 * s0, h1 + gt1 * s1);
                        int gio = gid[r] - g0;
                        float2 m2, i2;
                        if (gio < 3) {
                            m2 = *(const float2*)(pgm + gio * 128 + c);
                            i2 = *(const float2*)(pgi + gio * 128 + c);
                        } else {
                            int gg = gid[r];
                            m2 = *(const float2*)(g_gm + gg * D + c);
                            i2 = *(const float2*)(g_gisd + gg * D + c);
                        }
                        *(unsigned*)(Hb + r * LDH + c) =
                            pk((h0 - m2.x) * i2.x, (h1 - m2.y) * i2.y);
                        acc[mt][nt][rh * 2 + 0] = 0.f;
                        acc[mt][nt][rh * 2 + 1] = 0.f;
                    }
            __syncthreads();
            // coalesced h_fused store
            for (int idx = tid; idx < 128 * 16; idx += NT3) {
                int r2 = idx >> 4, f = idx & 15;
                if (r0 + r2 < N)
                    *(uint4*)(g_hfb + (size_t)(r0 + r2) * D + f * 8) =
                        *(const uint4*)(Eb + r2 * LDH + f * 8);
            }
        }

        if (k + 1 < 8) {
            load_wchunk<NT3>(((k + 1) & 1) ? Wq : Wp, Wtab[k + 1], tid);
            cp_commit();
        }
        bf16* buf = (k & 1) ? Wq : Wp;
        const bf16* A = (k < 2) ? Hb : (k < 6) ? Eb : Hb;
        mma_chunk16(acc, A, LDH, (k & 1) * 64, buf, wm, wn, lane);
    }

    // BN2 stats from fp32 accumulators
#pragma unroll
    for (int nt = 0; nt < 4; nt++)
#pragma unroll
        for (int par = 0; par < 2; par++) {
            int ccol = wn * 32 + nt * 8 + 2 * t4 + par;
            float bb = pbs1[ccol];
            float s1 = 0.f, s2 = 0.f;
#pragma unroll
            for (int mt = 0; mt < 2; mt++)
#pragma unroll
                for (int rh = 0; rh < 2; rh++) {
                    int r = r0 + wm * 32 + mt * 16 + g4 + rh * 8;
                    float val = acc[mt][nt][rh * 2 + par] + bb;
                    if (r < N) { s1 += val; s2 += val * val; }
                }
#pragma unroll
            for (int o = 4; o < 32; o <<= 1) {
                s1 += __shfl_xor_sync(0xffffffffu, s1, o);
                s2 += __shfl_xor_sync(0xffffffffu, s2, o);
            }
            if (g4 == 0) {
                atomicAdd(&g_bn2sum[ccol], s1);
                atomicAdd(&g_bn2sq[ccol], s2);
            }
        }

    // Z1 fragments -> Hb (distinct positions per warp)
#pragma unroll
    for (int mt = 0; mt < 2; mt++)
#pragma unroll
        for (int nt = 0; nt < 4; nt++)
#pragma unroll
            for (int rh = 0; rh < 2; rh++) {
                int r = wm * 32 + mt * 16 + g4 + rh * 8;
                int c = wn * 32 + nt * 8 + 2 * t4;
                float z0 = acc[mt][nt][rh * 2 + 0] + pbs1[c];
                float z1 = acc[mt][nt][rh * 2 + 1] + pbs1[c + 1];
                *(unsigned*)(Hb + r * LDH + c) = pk(z0, z1);
            }
    __syncthreads();

    // coalesced Z1 store
    for (int idx = tid; idx < 128 * 16; idx += NT3) {
        int r2 = idx >> 4, f = idx & 15;
        if (r0 + r2 < N)
            *(uint4*)(g_Z1b + (size_t)(r0 + r2) * D + f * 8) =
                *(const uint4*)(Hb + r2 * LDH + f * 8);
    }
}

// ---------------- K5: BN2 finalize + logits + exp + weighted segment sums ----------------
__global__ __launch_bounds__(256) void k_score(const int* __restrict__ batch,
                                               const float* __restrict__ g2,
                                               const float* __restrict__ be2,
                                               const float* __restrict__ Ws2,
                                               const float* __restrict__ bs2,
                                               float invN, int N) {
    __shared__ float es[256];
    __shared__ float sa2[128], sc2[128];
    __shared__ int gid[256];
    int tid = threadIdx.x, lane = tid & 31, warp = tid >> 5;
    int r0 = blockIdx.x * 256;
    int nr = min(256, N - r0);
    gid[tid] = batch[min(r0 + min(tid, nr - 1), N - 1)];
    if (tid < 128) {
        float gg = g2[tid];
        float mu = g_bn2sum[tid] * invN;
        float var = g_bn2sq[tid] * invN - mu * mu;
        float inv = rsqrtf(var + 1e-5f);
        sa2[tid] = gg * inv;
        sc2[tid] = be2[tid] - mu * gg * inv;
    }
    __syncthreads();

    float a2v[4], c2v[4], wv[4];
#pragma unroll
    for (int j = 0; j < 4; j++) {
        int c = 4 * lane + j;
        a2v[j] = sa2[c]; c2v[j] = sc2[c]; wv[j] = Ws2[c];
    }
    float bsv = bs2[0];

    int rbase = warp * 32;
    for (int rr = rbase; rr < rbase + 32; rr += 2) {
        float pA = 0.f, pB = 0.f;
        bool vA = (rr < nr), vB = (rr + 1 < nr);
        if (vA) {
            const bf16* z = g_Z1b + (size_t)(r0 + rr) * D + 4 * lane;
            unsigned u0 = *(const unsigned*)z, u1 = *(const unsigned*)(z + 2);
            float z0, z1, z2, z3; upk(u0, z0, z1); upk(u1, z2, z3);
            pA = fmaxf(a2v[0] * z0 + c2v[0], 0.f) * wv[0]
               + fmaxf(a2v[1] * z1 + c2v[1], 0.f) * wv[1]
               + fmaxf(a2v[2] * z2 + c2v[2], 0.f) * wv[2]
               + fmaxf(a2v[3] * z3 + c2v[3], 0.f) * wv[3];
        }
        if (vB) {
            const bf16* z = g_Z1b + (size_t)(r0 + rr + 1) * D + 4 * lane;
            unsigned u0 = *(const unsigned*)z, u1 = *(const unsigned*)(z + 2);
            float z0, z1, z2, z3; upk(u0, z0, z1); upk(u1, z2, z3);
            pB = fmaxf(a2v[0] * z0 + c2v[0], 0.f) * wv[0]
               + fmaxf(a2v[1] * z1 + c2v[1], 0.f) * wv[1]
               + fmaxf(a2v[2] * z2 + c2v[2], 0.f) * wv[2]
               + fmaxf(a2v[3] * z3 + c2v[3], 0.f) * wv[3];
        }
#pragma unroll
        for (int o = 16; o > 0; o >>= 1) {
            pA += __shfl_xor_sync(0xffffffffu, pA, o);
            pB += __shfl_xor_sync(0xffffffffu, pB, o);
        }
        if (lane == 0) {
            es[rr] = vA ? __expf(pA + bsv) : 0.f;
            es[rr + 1] = vB ? __expf(pB + bsv) : 0.f;
        }
    }
    __syncthreads();

    {
        int p2 = tid & 63;
        int c = 2 * p2;
        int q = tid >> 6;
        int rb = q * 64;
        float an0 = 0.f, an1 = 0.f, ad = 0.f;
        int cur = gid[rb];
        for (int i = 0; i < 64; i += 4) {
            unsigned u[4]; float e[4];
#pragma unroll
            for (int j = 0; j < 4; j++) {
                int rr = rb + i + j;
                int r = r0 + rr;
                u[j] = (r < N) ? *(const unsigned*)(g_hfb + (size_t)r * D + c) : 0u;
                e[j] = es[rr];
            }
#pragma unroll
            for (int j = 0; j < 4; j++) {
                int rr = rb + i + j;
                int g = gid[rr];
                if (g != cur) {
                    atomicAdd(&g_num[cur * D + c], an0);
                    atomicAdd(&g_num[cur * D + c + 1], an1);
                    if (p2 == 0) atomicAdd(&g_den[cur], ad);
                    an0 = an1 = ad = 0.f;
                    cur = g;
                }
                if (r0 + rr < N) {
                    float v0, v1; upk(u[j], v0, v1);
                    an0 += e[j] * v0; an1 += e[j] * v1; ad += e[j];
                }
            }
        }
        atomicAdd(&g_num[cur * D + c], an0);
        atomicAdd(&g_num[cur * D + c + 1], an1);
        if (p2 == 0) atomicAdd(&g_den[cur], ad);
    }
}

// ---------------- K6: final combine ----------------
__global__ void k_out(float* __restrict__ out, const float* __restrict__ mix) {
    int i = blockIdx.x * blockDim.x + threadIdx.x;
    if (i >= G * D) return;
    int g = i / D;
    float alpha = 1.f / (1.f + expf(-mix[0]));
    float den = g_den[g];
    float wf = (den > 0.f) ? (g_num[i] / den) : 0.f;
    out[i] = alpha * wf + (1.f - alpha) * g_gm[i];
}

// ---------------- launch ----------------
extern "C" void kernel_launch(void* const* d_in, const int* in_sizes, int n_in,
                              void* d_out, int out_size) {
    const float* h   = (const float*)d_in[0];
    const float* sub = (const float*)d_in[1];
    const int* batch = (const int*)d_in[2];
    const float* W1  = (const float*)d_in[3];
    const float* b1  = (const float*)d_in[4];
    const float* g1  = (const float*)d_in[5];
    const float* be1 = (const float*)d_in[6];
    const float* Wg  = (const float*)d_in[7];
    const float* bg  = (const float*)d_in[8];
    const float* Ws1 = (const float*)d_in[9];
    const float* bs1 = (const float*)d_in[10];
    const float* g2  = (const float*)d_in[11];
    const float* be2 = (const float*)d_in[12];
    const float* Ws2 = (const float*)d_in[13];
    const float* bs2 = (const float*)d_in[14];
    const float* mix = (const float*)d_in[15];
    float* out = (float*)d_out;

    int N = in_sizes[0] / D;
    if (N > NMAX) N = NMAX;

    const int SMEM_P1 = 2 * 128 * LDWB * 2 + 512;
    const int SMEM_K3 = (2 * 128 * LDH + 2 * 128 * LDWB) * 2 + 5 * D * 4 + 512
                      + 2 * 3 * 128 * 4;
    cudaFuncSetAttribute(k_pass1, cudaFuncAttributeMaxDynamicSharedMemorySize, SMEM_P1);
    cudaFuncSetAttribute(k_fused, cudaFuncAttributeMaxDynamicSharedMemorySize, SMEM_K3);

    int nb = (N + 127) / 128;
    int nb2 = (N + 255) / 256;
    float invN = 1.f / (float)N;
    k_init<<<(4 * D * S + 255) / 256, 256>>>(W1, Wg, Ws1);
    k_pass1<<<nb, NT1, SMEM_P1>>>(h, sub, batch, b1, N);
    k_mid<<<(G * D + 255) / 256, 256>>>(g1, be1, invN);
    k_fused<<<nb, NT3, SMEM_K3>>>(batch, b1, bg, bs1, N);
    k_score<<<nb2, 256>>>(batch, g2, be2, Ws2, bs2, invN, N);
    k_out<<<(G * D + 255) / 256, 256>>>(out, mix);
}